// round 12
// baseline (speedup 1.0000x reference)
#include <cuda_runtime.h>
#include <math.h>
#include <stdint.h>

#define N_NODES 100000
#define N_EDGES 400000
#define E_TOT   500000
#define N_GRAPHS 2048
#define F_IN 78
#define H1N 10
#define C1  780      // 10*78
#define C1P 800      // padded: 10 heads * 80
#define OUT2 128
#define NB_SCAN 98   // ceil(100000/1024)

// ---------------- scratch (device globals; no allocation allowed) -----------
__device__ __align__(16) float g_XAGG[(N_NODES + 32) * C1P]; // pitch-80/head, 100032 rows
__device__ __align__(16) float g_H2[N_NODES * OUT2];
__device__ float g_ASD1[N_NODES * 2 * H1N];
__device__ float g_AS2[N_NODES], g_AD2[N_NODES];
__device__ int   g_DEG[N_NODES], g_INCL[N_NODES], g_BSUM[128], g_BOFF[128];
__device__ int   g_OFF[N_NODES + 1], g_CUR[N_NODES], g_CSRC[E_TOT];
__device__ float g_WATT[F_IN * 2 * H1N];
__device__ __align__(16) float g_W1P[F_IN * C1P];   // W1 re-laid, pitch 80/head (pad cols stay 0)
__device__ float g_W2AS[C1], g_W2AD[C1];
__device__ float g_HSUM[N_GRAPHS * OUT2], g_HMAX[N_GRAPHS * OUT2];
__device__ __align__(16) float g_XT[N_GRAPHS * 256];
__device__ __align__(16) float g_XC[N_GRAPHS * 512];
__device__ __align__(16) float g_X1[N_GRAPHS * 1024];
__device__ __align__(16) float g_X2[N_GRAPHS * 256];

// ---------------- CSR build -----------------------------------------------
__global__ void k_initdeg() {
    int i = blockIdx.x * blockDim.x + threadIdx.x;
    if (i < N_NODES) g_DEG[i] = 1;
}
__global__ void k_hist(const int* __restrict__ ei) {
    int e = blockIdx.x * blockDim.x + threadIdx.x;
    if (e < N_EDGES) atomicAdd(&g_DEG[ei[N_EDGES + e]], 1);
}
__global__ void k_scan1() {
    __shared__ int sw[32];
    int i = blockIdx.x * 1024 + threadIdx.x;
    int v = (i < N_NODES) ? g_DEG[i] : 0;
    int lane = threadIdx.x & 31, w = threadIdx.x >> 5;
    int x = v;
#pragma unroll
    for (int o = 1; o < 32; o <<= 1) {
        int y = __shfl_up_sync(0xffffffffu, x, o);
        if (lane >= o) x += y;
    }
    if (lane == 31) sw[w] = x;
    __syncthreads();
    if (w == 0) {
        int s = sw[lane];
#pragma unroll
        for (int o = 1; o < 32; o <<= 1) {
            int y = __shfl_up_sync(0xffffffffu, s, o);
            if (lane >= o) s += y;
        }
        sw[lane] = s;
    }
    __syncthreads();
    if (w > 0) x += sw[w - 1];
    if (i < N_NODES) g_INCL[i] = x;
    if (threadIdx.x == 1023) g_BSUM[blockIdx.x] = x;
}
__global__ void k_scan2() {
    __shared__ int sw[4];
    int t = threadIdx.x;
    int v = (t < NB_SCAN) ? g_BSUM[t] : 0;
    int lane = t & 31, w = t >> 5;
    int x = v;
#pragma unroll
    for (int o = 1; o < 32; o <<= 1) {
        int y = __shfl_up_sync(0xffffffffu, x, o);
        if (lane >= o) x += y;
    }
    if (lane == 31) sw[w] = x;
    __syncthreads();
    int add = 0;
    for (int i = 0; i < w; i++) add += sw[i];
    x += add;
    if (t < NB_SCAN) g_BOFF[t] = x - v;
}
__global__ void k_scan3() {
    int i = blockIdx.x * blockDim.x + threadIdx.x;
    if (i < N_NODES) {
        int off = g_INCL[i] - g_DEG[i] + g_BOFF[i >> 10];
        g_OFF[i] = off;
        g_CUR[i] = off;
        if (i == 0) g_OFF[N_NODES] = E_TOT;
    }
}
__global__ void k_scatter(const int* __restrict__ ei) {
    int i = blockIdx.x * blockDim.x + threadIdx.x;
    if (i >= E_TOT) return;
    int s, d;
    if (i < N_EDGES) { s = ei[i]; d = ei[N_EDGES + i]; }
    else             { s = d = i - N_EDGES; }
    int pos = atomicAdd(&g_CUR[d], 1);
    g_CSRC[pos] = s;
}

// ---------------- zero-init ----------------------------------------------
__global__ void k_zero() {
    int i = blockIdx.x * blockDim.x + threadIdx.x;
    if (i < N_GRAPHS * OUT2) { g_HSUM[i] = 0.f; g_HMAX[i] = 0.f; }
    if (i < N_NODES) { g_AS2[i] = 0.f; g_AD2[i] = 0.f; }
}

// ---------------- weight prep ----------------------------------------------
__global__ void k_prep_att(const float* __restrict__ W1, const float* __restrict__ as,
                           const float* __restrict__ ad) {
    int i = blockIdx.x * blockDim.x + threadIdx.x;
    if (i >= F_IN * 2 * H1N) return;
    int k = i / (2 * H1N), j = i - k * (2 * H1N);
    const float* a = (j < H1N) ? (as + j * F_IN) : (ad + (j - H1N) * F_IN);
    int h = (j < H1N) ? j : j - H1N;
    float s = 0.f;
    for (int d = 0; d < F_IN; d++) s += W1[k * C1 + h * F_IN + d] * a[d];
    g_WATT[i] = s;
}
__global__ void k_prep_w1p(const float* __restrict__ W1) {
    int i = blockIdx.x * blockDim.x + threadIdx.x;
    if (i >= F_IN * C1) return;
    int k = i / C1, c = i - k * C1;
    int h = c / F_IN, d = c - h * F_IN;
    g_W1P[k * C1P + h * 80 + d] = W1[i];
}
__global__ void k_prep2v(const float* __restrict__ W2, const float* __restrict__ as,
                         const float* __restrict__ ad) {
    int k = blockIdx.x * blockDim.x + threadIdx.x;
    if (k >= C1) return;
    float s = 0.f, t = 0.f;
    for (int d = 0; d < OUT2; d++) {
        float w = W2[k * OUT2 + d];
        s = fmaf(w, as[d], s);
        t = fmaf(w, ad[d], t);
    }
    g_W2AS[k] = s;
    g_W2AD[k] = t;
}

// ---------------- attention logits ------------------------------------------
__global__ void k_att1(const float* __restrict__ x) {
    __shared__ float sW[F_IN * 2 * H1N];
    __shared__ float sX[8 * F_IN];
    int tid = threadIdx.x, w = tid >> 5, lane = tid & 31;
    for (int i = tid; i < F_IN * 2 * H1N; i += 256) sW[i] = g_WATT[i];
    int n = blockIdx.x * 8 + w;
    if (n < N_NODES) {
        for (int d = lane; d < F_IN; d += 32) sX[w * F_IN + d] = x[(size_t)n * F_IN + d];
    }
    __syncthreads();
    if (n >= N_NODES || lane >= 2 * H1N) return;
    float s = 0.f;
    for (int d = 0; d < F_IN; d++)
        s = fmaf(sX[w * F_IN + d], sW[d * 2 * H1N + lane], s);
    g_ASD1[n * 2 * H1N + lane] = s;
}

// ---------------- layer 1: fused softmax + x-space aggregation (warp/node) --
__global__ void k_aggx_w(const float* __restrict__ x) {
    int n = blockIdx.x * 8 + (threadIdx.x >> 5);
    if (n >= N_NODES) return;
    int lane = threadIdx.x & 31;
    int p0 = g_OFF[n], p1 = g_OFF[n + 1];
    float adst = (lane < H1N) ? g_ASD1[n * 2 * H1N + H1N + lane] : 0.f;
    float m = -1e30f;
    for (int p = p0; p < p1; p++) {
        int s = g_CSRC[p];
        if (lane < H1N) {
            float e = g_ASD1[s * 2 * H1N + lane] + adst;
            e = e > 0.f ? e : 0.2f * e;
            m = fmaxf(m, e);
        }
    }
    float den = 0.f;
    for (int p = p0; p < p1; p++) {
        int s = g_CSRC[p];
        if (lane < H1N) {
            float e = g_ASD1[s * 2 * H1N + lane] + adst;
            e = e > 0.f ? e : 0.2f * e;
            den += expf(e - m);
        }
    }
    float rd = 1.f / (den + 1e-16f);
    float acc[H1N][3];
#pragma unroll
    for (int h = 0; h < H1N; h++) { acc[h][0] = 0.f; acc[h][1] = 0.f; acc[h][2] = 0.f; }
    for (int p = p0; p < p1; p++) {
        int s = g_CSRC[p];
        float al = 0.f;
        if (lane < H1N) {
            float e = g_ASD1[s * 2 * H1N + lane] + adst;
            e = e > 0.f ? e : 0.2f * e;
            al = expf(e - m) * rd;
        }
        const float* xr = &x[(size_t)s * F_IN];
        float xv0 = xr[lane];
        float xv1 = xr[32 + lane];
        float xv2 = (lane < F_IN - 64) ? xr[64 + lane] : 0.f;
#pragma unroll
        for (int h = 0; h < H1N; h++) {
            float a = __shfl_sync(0xffffffffu, al, h);
            acc[h][0] = fmaf(a, xv0, acc[h][0]);
            acc[h][1] = fmaf(a, xv1, acc[h][1]);
            acc[h][2] = fmaf(a, xv2, acc[h][2]);
        }
    }
    size_t base = (size_t)n * C1P;
#pragma unroll
    for (int h = 0; h < H1N; h++) {
        g_XAGG[base + h * 80 + lane] = acc[h][0];
        g_XAGG[base + h * 80 + 32 + lane] = acc[h][1];
        if (lane < F_IN - 64) g_XAGG[base + h * 80 + 64 + lane] = acc[h][2];
    }
}

// ---------------- helpers ----------------------------------------------------
__device__ __forceinline__ uint32_t f2tf32(float v) {
    uint32_t u;
    asm("cvt.rna.tf32.f32 %0, %1;" : "=r"(u) : "f"(v));
    return u;
}
__device__ __forceinline__ void cp16(void* dst, const float* src) {
    uint32_t d = (uint32_t)__cvta_generic_to_shared(dst);
    asm volatile("cp.async.cg.shared.global [%0], [%1], 16;\n" :: "r"(d), "l"(src));
}
__device__ __forceinline__ void cp16n(void* dst, const float* src, int nbytes) {
    uint32_t d = (uint32_t)__cvta_generic_to_shared(dst);
    asm volatile("cp.async.cg.shared.global [%0], [%1], 16, %2;\n" :: "r"(d), "l"(src), "r"(nbytes));
}
#define MMA_TF32(ACC, A0, A1, A2, A3, B0, B1)                                   \
    asm volatile(                                                               \
        "mma.sync.aligned.m16n8k8.row.col.f32.tf32.tf32.f32 "                   \
        "{%0,%1,%2,%3}, {%4,%5,%6,%7}, {%8,%9}, {%0,%1,%2,%3};\n"               \
        : "+f"(ACC[0]), "+f"(ACC[1]), "+f"(ACC[2]), "+f"(ACC[3])                \
        : "r"(A0), "r"(A1), "r"(A2), "r"(A3), "r"(B0), "r"(B1))

// ---------------- FUSED layer1 GEMM + ELU + layer2 GEMM ----------------------
#define FPA 84
#define FPW1 104
#define FPT 84
#define FPW2 136
#define OFF_A  0
#define OFF_W1 5376
#define OFF_T  13696
#define OFF_W2 19072
#define OFF_B1 40832
#define OFF_WS 40992
#define OFF_WD 41152
#define FUSED_SMEM_FLOATS 41312

__global__ void __launch_bounds__(256) k_fused(
    const float* __restrict__ XAGG, const float* __restrict__ W1P,
    const float* __restrict__ W2, const float* __restrict__ b1,
    const float* __restrict__ W2AS, const float* __restrict__ W2AD,
    float* __restrict__ H2, float* __restrict__ AS2, float* __restrict__ AD2) {
    extern __shared__ __align__(16) float sm[];
    float* sA  = sm + OFF_A;
    float* sW1 = sm + OFF_W1;
    float* sT  = sm + OFF_T;
    float* sW2 = sm + OFF_W2;
    float* sb1 = sm + OFF_B1;
    float* sws = sm + OFF_WS;
    float* swd = sm + OFF_WD;

    int t = threadIdx.x;
    int warp = t >> 5, lane = t & 31, g = lane >> 2, tg = lane & 3;
    int w1m = warp >> 1, w1n = warp & 1;   // stage1: 4x2 warps -> 64x80
    int wm = warp >> 2, wn = warp & 3;     // stage2: 2x4 warps -> 64x128
    int r0 = blockIdx.x * 64;

    auto issue_loads = [&](int h, int buf) {
#pragma unroll
        for (int i = 0; i < 5; i++) {
            int id = t + i * 256;
            int r = id / 20, c4 = id % 20;
            cp16(&sA[r * FPA + c4 * 4], XAGG + (size_t)(r0 + r) * C1P + h * 80 + c4 * 4);
        }
#pragma unroll
        for (int i = 0; i < 7; i++) {
            int id = t + i * 256;
            if (id < 1600) {
                int r = id / 20, c4 = id % 20;
                int rr = r < F_IN ? r : F_IN - 1;   // pad rows hit zero A-cols
                cp16(&sW1[r * FPW1 + c4 * 4], W1P + (size_t)rr * C1P + h * 80 + c4 * 4);
            }
        }
        float* w2d = sW2 + buf * (80 * FPW2);
#pragma unroll
        for (int i = 0; i < 10; i++) {
            int id = t + i * 256;
            int r = id >> 5, c4 = id & 31;
            int rr = h * F_IN + r;
            if (rr > C1 - 1) rr = C1 - 1;           // pad rows hit zero T-cols
            cp16(&w2d[r * FPW2 + c4 * 4], W2 + (size_t)rr * OUT2 + c4 * 4);
        }
        if (t < 80) {
            int c = h * F_IN + t;
            sb1[buf * 80 + t] = (t < F_IN) ? b1[c] : 0.f;
            sws[buf * 80 + t] = (t < F_IN) ? W2AS[c] : 0.f;
            swd[buf * 80 + t] = (t < F_IN) ? W2AD[c] : 0.f;
        }
        asm volatile("cp.async.commit_group;\n");
    };

    issue_loads(0, 0);

    float acc2[2][4][4];
#pragma unroll
    for (int mi = 0; mi < 2; mi++)
#pragma unroll
        for (int ni = 0; ni < 4; ni++)
#pragma unroll
            for (int r = 0; r < 4; r++) acc2[mi][ni][r] = 0.f;
    float ps0 = 0.f, ps1 = 0.f, pd0 = 0.f, pd1 = 0.f;

    int buf = 0;
    for (int h = 0; h < H1N; h++) {
        asm volatile("cp.async.wait_group 0;\n");
        __syncthreads();
        // ---- stage 1 ----
        float acc1[5][4];
#pragma unroll
        for (int ni = 0; ni < 5; ni++)
#pragma unroll
            for (int r = 0; r < 4; r++) acc1[ni][r] = 0.f;
        int br1 = w1m * 16;
#pragma unroll
        for (int kk = 0; kk < 80; kk += 8) {
            uint32_t a0 = f2tf32(sA[(br1 + g) * FPA + kk + tg]);
            uint32_t a1 = f2tf32(sA[(br1 + g + 8) * FPA + kk + tg]);
            uint32_t a2 = f2tf32(sA[(br1 + g) * FPA + kk + tg + 4]);
            uint32_t a3 = f2tf32(sA[(br1 + g + 8) * FPA + kk + tg + 4]);
#pragma unroll
            for (int ni = 0; ni < 5; ni++) {
                int bc = w1n * 40 + ni * 8 + g;
                uint32_t b0 = f2tf32(sW1[(kk + tg) * FPW1 + bc]);
                uint32_t bb = f2tf32(sW1[(kk + tg + 4) * FPW1 + bc]);
                MMA_TF32(acc1[ni], a0, a1, a2, a3, b0, bb);
            }
        }
        {
            int rr0 = w1m * 16 + g, rr1 = rr0 + 8;
            const float* bbp = &sb1[buf * 80];
            const float* wsp = &sws[buf * 80];
            const float* wdp = &swd[buf * 80];
#pragma unroll
            for (int ni = 0; ni < 5; ni++) {
                int c = w1n * 40 + ni * 8 + tg * 2;
                float b0v = bbp[c], b1v = bbp[c + 1];
                float v0 = acc1[ni][0] + b0v; v0 = v0 > 0.f ? v0 : expm1f(v0);
                float v1 = acc1[ni][1] + b1v; v1 = v1 > 0.f ? v1 : expm1f(v1);
                float v2 = acc1[ni][2] + b0v; v2 = v2 > 0.f ? v2 : expm1f(v2);
                float v3 = acc1[ni][3] + b1v; v3 = v3 > 0.f ? v3 : expm1f(v3);
                float s0 = wsp[c], s1 = wsp[c + 1], d0 = wdp[c], d1 = wdp[c + 1];
                ps0 = fmaf(v0, s0, fmaf(v1, s1, ps0));
                pd0 = fmaf(v0, d0, fmaf(v1, d1, pd0));
                ps1 = fmaf(v2, s0, fmaf(v3, s1, ps1));
                pd1 = fmaf(v2, d0, fmaf(v3, d1, pd1));
                *(float2*)&sT[rr0 * FPT + c] = make_float2(v0, v1);
                *(float2*)&sT[rr1 * FPT + c] = make_float2(v2, v3);
            }
        }
        __syncthreads();
        if (h + 1 < H1N) issue_loads(h + 1, buf ^ 1);
        // ---- stage 2 ----
        const float* w2s = sW2 + buf * (80 * FPW2);
#pragma unroll
        for (int kk = 0; kk < 80; kk += 8) {
            uint32_t af[2][4];
#pragma unroll
            for (int mi = 0; mi < 2; mi++) {
                int br = wm * 32 + mi * 16;
                af[mi][0] = f2tf32(sT[(br + g) * FPT + kk + tg]);
                af[mi][1] = f2tf32(sT[(br + g + 8) * FPT + kk + tg]);
                af[mi][2] = f2tf32(sT[(br + g) * FPT + kk + tg + 4]);
                af[mi][3] = f2tf32(sT[(br + g + 8) * FPT + kk + tg + 4]);
            }
#pragma unroll
            for (int ni = 0; ni < 4; ni++) {
                int bc = wn * 32 + ni * 8 + g;
                uint32_t b0 = f2tf32(w2s[(kk + tg) * FPW2 + bc]);
                uint32_t bb = f2tf32(w2s[(kk + tg + 4) * FPW2 + bc]);
                MMA_TF32(acc2[0][ni], af[0][0], af[0][1], af[0][2], af[0][3], b0, bb);
                MMA_TF32(acc2[1][ni], af[1][0], af[1][1], af[1][2], af[1][3], b0, bb);
            }
        }
        __syncthreads();
        buf ^= 1;
    }
#pragma unroll
    for (int mi = 0; mi < 2; mi++) {
#pragma unroll
        for (int half = 0; half < 2; half++) {
            int row = r0 + wm * 32 + mi * 16 + g + half * 8;
            if (row < N_NODES) {
#pragma unroll
                for (int ni = 0; ni < 4; ni++) {
                    int col = wn * 32 + ni * 8 + tg * 2;
                    *(float2*)&H2[(size_t)row * OUT2 + col] =
                        make_float2(acc2[mi][ni][half * 2], acc2[mi][ni][half * 2 + 1]);
                }
            }
        }
    }
    ps0 += __shfl_xor_sync(0xffffffffu, ps0, 1); ps0 += __shfl_xor_sync(0xffffffffu, ps0, 2);
    pd0 += __shfl_xor_sync(0xffffffffu, pd0, 1); pd0 += __shfl_xor_sync(0xffffffffu, pd0, 2);
    ps1 += __shfl_xor_sync(0xffffffffu, ps1, 1); ps1 += __shfl_xor_sync(0xffffffffu, ps1, 2);
    pd1 += __shfl_xor_sync(0xffffffffu, pd1, 1); pd1 += __shfl_xor_sync(0xffffffffu, pd1, 2);
    if (tg == 0) {
        int ra = r0 + w1m * 16 + g;
        if (ra < N_NODES) { atomicAdd(&AS2[ra], ps0); atomicAdd(&AD2[ra], pd0); }
        int rb = ra + 8;
        if (rb < N_NODES) { atomicAdd(&AS2[rb], ps1); atomicAdd(&AD2[rb], pd1); }
    }
}

// ---------------- TF32 GEMM (tail MLP): 64x128 tile, cp.async 2-stage --------
#define PAp 20
#define PBp 136
__global__ void __launch_bounds__(256) k_mma3(
    const float* __restrict__ A, const float* __restrict__ B,
    const float* __restrict__ bias, float* __restrict__ C,
    int M, int K, int N, int lda, int ldb, int ldC, int act) {
    __shared__ __align__(16) float sA[2][64 * PAp];
    __shared__ __align__(16) float sB[2][16 * PBp];
    int t = threadIdx.x;
    int warp = t >> 5, lane = t & 31;
    int g = lane >> 2, tg = lane & 3;
    int wm = warp >> 2, wn = warp & 3;
    int r0 = blockIdx.x * 64;
    int c0 = blockIdx.y * 128;

    int arow = t >> 2, acol = (t & 3) * 4;
    const float* aptr = A + (size_t)(r0 + arow) * lda + acol;
    int brow[2], bcol[2];
#pragma unroll
    for (int i = 0; i < 2; i++) {
        int id = t + i * 256;
        brow[i] = id >> 5;
        bcol[i] = (id & 31) * 4;
    }

    int niter = (K + 15) / 16;
    {
        cp16n(&sA[0][arow * PAp + acol], aptr, 16);
#pragma unroll
        for (int i = 0; i < 2; i++) {
            const float* src = B + (size_t)brow[i] * ldb + c0 + bcol[i];
            int nb = 0;
            if (brow[i] < K) {
                int v = N - (c0 + bcol[i]);
                nb = v >= 4 ? 16 : (v > 0 ? v * 4 : 0);
            }
            if (nb == 0) src = B;
            cp16n(&sB[0][brow[i] * PBp + bcol[i]], src, nb);
        }
        asm volatile("cp.async.commit_group;\n");
    }

    float acc[2][4][4];
#pragma unroll
    for (int mi = 0; mi < 2; mi++)
#pragma unroll
        for (int ni = 0; ni < 4; ni++)
#pragma unroll
            for (int r = 0; r < 4; r++) acc[mi][ni][r] = 0.f;

    for (int it = 0; it < niter; it++) {
        if (it + 1 < niter) {
            int kt = (it + 1) * 16;
            int bufp = (it + 1) & 1;
            cp16n(&sA[bufp][arow * PAp + acol], aptr + kt, 16);
#pragma unroll
            for (int i = 0; i < 2; i++) {
                const float* src = B + (size_t)(kt + brow[i]) * ldb + c0 + bcol[i];
                int nb = 0;
                if (kt + brow[i] < K) {
                    int v = N - (c0 + bcol[i]);
                    nb = v >= 4 ? 16 : (v > 0 ? v * 4 : 0);
                }
                if (nb == 0) src = B;
                cp16n(&sB[bufp][brow[i] * PBp + bcol[i]], src, nb);
            }
            asm volatile("cp.async.commit_group;\n");
            asm volatile("cp.async.wait_group 1;\n");
        } else {
            asm volatile("cp.async.wait_group 0;\n");
        }
        __syncthreads();
        int cb = it & 1;
#pragma unroll
        for (int kk = 0; kk < 16; kk += 8) {
            uint32_t af[2][4];
#pragma unroll
            for (int mi = 0; mi < 2; mi++) {
                int br = wm * 32 + mi * 16;
                af[mi][0] = f2tf32(sA[cb][(br + g) * PAp + kk + tg]);
                af[mi][1] = f2tf32(sA[cb][(br + g + 8) * PAp + kk + tg]);
                af[mi][2] = f2tf32(sA[cb][(br + g) * PAp + kk + tg + 4]);
                af[mi][3] = f2tf32(sA[cb][(br + g + 8) * PAp + kk + tg + 4]);
            }
#pragma unroll
            for (int ni = 0; ni < 4; ni++) {
                int bc = wn * 32 + ni * 8 + g;
                uint32_t b0 = f2tf32(sB[cb][(kk + tg) * PBp + bc]);
                uint32_t bb = f2tf32(sB[cb][(kk + tg + 4) * PBp + bc]);
                MMA_TF32(acc[0][ni], af[0][0], af[0][1], af[0][2], af[0][3], b0, bb);
                MMA_TF32(acc[1][ni], af[1][0], af[1][1], af[1][2], af[1][3], b0, bb);
            }
        }
        __syncthreads();
    }
#pragma unroll
    for (int mi = 0; mi < 2; mi++) {
#pragma unroll
        for (int half = 0; half < 2; half++) {
            int row = r0 + wm * 32 + mi * 16 + g + half * 8;
            if (row >= M) continue;
#pragma unroll
            for (int ni = 0; ni < 4; ni++) {
                int col = c0 + wn * 32 + ni * 8 + tg * 2;
#pragma unroll
                for (int q = 0; q < 2; q++) {
                    if (col + q < N) {
                        float v = acc[mi][ni][half * 2 + q] + (bias ? bias[col + q] : 0.f);
                        if (act == 1) v = fmaxf(v, 0.f);
                        C[(size_t)row * ldC + col + q] = v;
                    }
                }
            }
        }
    }
}

// ---------------- layer 2: fused softmax + aggregation + readout ------------
__global__ void k_agg2_w(const float* __restrict__ b2, const float* __restrict__ wg,
                         const float* __restrict__ bg, const int* __restrict__ batch) {
    int n = blockIdx.x * 8 + (threadIdx.x >> 5);
    if (n >= N_NODES) return;
    int lane = threadIdx.x & 31;
    int p0 = g_OFF[n], p1 = g_OFF[n + 1];
    float adst = g_AD2[n];
    float m = -1e30f;
    for (int p = p0; p < p1; p++) {
        float e = g_AS2[g_CSRC[p]] + adst;
        e = e > 0.f ? e : 0.2f * e;
        m = fmaxf(m, e);
    }
    float den = 0.f;
    for (int p = p0; p < p1; p++) {
        float e = g_AS2[g_CSRC[p]] + adst;
        e = e > 0.f ? e : 0.2f * e;
        den += expf(e - m);
    }
    float rd = 1.f / (den + 1e-16f);
    float a0 = 0.f, a1 = 0.f, a2 = 0.f, a3 = 0.f;
    for (int p = p0; p < p1; p++) {
        int s = g_CSRC[p];
        float e = g_AS2[s] + adst;
        e = e > 0.f ? e : 0.2f * e;
        float al = expf(e - m) * rd;
        const float* hr = &g_H2[(size_t)s * OUT2];
        a0 = fmaf(al, hr[lane], a0);
        a1 = fmaf(al, hr[32 + lane], a1);
        a2 = fmaf(al, hr[64 + lane], a2);
        a3 = fmaf(al, hr[96 + lane], a3);
    }
    float v0 = fmaxf(a0 + b2[lane], 0.f);
    float v1 = fmaxf(a1 + b2[32 + lane], 0.f);
    float v2 = fmaxf(a2 + b2[64 + lane], 0.f);
    float v3 = fmaxf(a3 + b2[96 + lane], 0.f);
    float gp = v0 * wg[lane] + v1 * wg[32 + lane] + v2 * wg[64 + lane] + v3 * wg[96 + lane];
#pragma unroll
    for (int o = 16; o > 0; o >>= 1) gp += __shfl_xor_sync(0xffffffffu, gp, o);
    float w = 1.f / (1.f + expf(-(gp + bg[0])));
    int gr = batch[n];
    float* hs = &g_HSUM[(size_t)gr * OUT2];
    float* hm = &g_HMAX[(size_t)gr * OUT2];
    atomicAdd(&hs[lane], v0 * w);
    atomicAdd(&hs[32 + lane], v1 * w);
    atomicAdd(&hs[64 + lane], v2 * w);
    atomicAdd(&hs[96 + lane], v3 * w);
    atomicMax((int*)&hm[lane], __float_as_int(v0));
    atomicMax((int*)&hm[32 + lane], __float_as_int(v1));
    atomicMax((int*)&hm[64 + lane], __float_as_int(v2));
    atomicMax((int*)&hm[96 + lane], __float_as_int(v3));
}

// ---------------- tail ------------------------------------------------------
__global__ void k_concat() {
    int i = blockIdx.x * blockDim.x + threadIdx.x;
    if (i >= N_GRAPHS * 512) return;
    int g = i / 512, c = i - g * 512;
    float v;
    if (c < 128)      v = g_HSUM[g * 128 + c];
    else if (c < 256) v = g_HMAX[g * 128 + (c - 128)];
    else              v = g_XT[g * 256 + (c - 256)];
    g_XC[i] = v;
}
__global__ void k_out(const float* __restrict__ Wo, const float* __restrict__ bo,
                      float* __restrict__ out) {
    int g = blockIdx.x, lane = threadIdx.x;
    float s = 0.f;
    for (int k = lane; k < 256; k += 32) s += g_X2[g * 256 + k] * Wo[k];
#pragma unroll
    for (int o = 16; o > 0; o >>= 1) s += __shfl_down_sync(0xffffffffu, s, o);
    if (lane == 0) out[g] = s + bo[0];
}

// ---------------- host ------------------------------------------------------
static inline dim3 mma_grid(int M, int N) {
    return dim3((M + 63) / 64, (N + 127) / 128);
}

extern "C" void kernel_launch(void* const* d_in, const int* in_sizes, int n_in,
                              void* d_out, int out_size) {
    const float* x      = (const float*)d_in[0];
    const int*   ei     = (const int*)d_in[1];
    const int*   batch  = (const int*)d_in[2];
    const float* target = (const float*)d_in[3];
    const float* W1  = (const float*)d_in[4];
    const float* as1 = (const float*)d_in[5];
    const float* ad1 = (const float*)d_in[6];
    const float* b1  = (const float*)d_in[7];
    const float* W2  = (const float*)d_in[8];
    const float* as2 = (const float*)d_in[9];
    const float* ad2 = (const float*)d_in[10];
    const float* b2  = (const float*)d_in[11];
    const float* wg  = (const float*)d_in[12];
    const float* bg  = (const float*)d_in[13];
    const float* Wxt = (const float*)d_in[14];
    const float* bxt = (const float*)d_in[15];
    const float* Wf1 = (const float*)d_in[16];
    const float* bf1 = (const float*)d_in[17];
    const float* Wf2 = (const float*)d_in[18];
    const float* bf2 = (const float*)d_in[19];
    const float* Wo  = (const float*)d_in[20];
    const float* bo  = (const float*)d_in[21];
    float* out = (float*)d_out;

    float *XAGG, *H2, *W1P, *W2AS, *W2AD, *AS2, *AD2, *XT, *XC, *X1, *X2;
    cudaGetSymbolAddress((void**)&XAGG, g_XAGG);
    cudaGetSymbolAddress((void**)&H2,  g_H2);
    cudaGetSymbolAddress((void**)&W1P, g_W1P);
    cudaGetSymbolAddress((void**)&W2AS, g_W2AS);
    cudaGetSymbolAddress((void**)&W2AD, g_W2AD);
    cudaGetSymbolAddress((void**)&AS2, g_AS2);
    cudaGetSymbolAddress((void**)&AD2, g_AD2);
    cudaGetSymbolAddress((void**)&XT,  g_XT);
    cudaGetSymbolAddress((void**)&XC,  g_XC);
    cudaGetSymbolAddress((void**)&X1,  g_X1);
    cudaGetSymbolAddress((void**)&X2,  g_X2);

    cudaFuncSetAttribute(k_fused, cudaFuncAttributeMaxDynamicSharedMemorySize,
                         FUSED_SMEM_FLOATS * 4);

    // CSR build + zero accumulators
    k_initdeg<<<(N_NODES + 255) / 256, 256>>>();
    k_hist<<<(N_EDGES + 255) / 256, 256>>>(ei);
    k_scan1<<<NB_SCAN, 1024>>>();
    k_scan2<<<1, 128>>>();
    k_scan3<<<(N_NODES + 255) / 256, 256>>>();
    k_scatter<<<(E_TOT + 255) / 256, 256>>>(ei);
    k_zero<<<(N_GRAPHS * OUT2 + 255) / 256, 256>>>();

    // weight prep
    k_prep_att<<<(F_IN * 2 * H1N + 255) / 256, 256>>>(W1, as1, ad1);
    k_prep_w1p<<<(F_IN * C1 + 255) / 256, 256>>>(W1);
    k_prep2v<<<(C1 + 255) / 256, 256>>>(W2, as2, ad2);

    // layer 1+2 fused path
    k_att1<<<(N_NODES + 7) / 8, 256>>>(x);
    k_aggx_w<<<(N_NODES + 7) / 8, 256>>>(x);
    k_fused<<<(N_NODES + 63) / 64, 256, FUSED_SMEM_FLOATS * 4>>>(
        XAGG, W1P, W2, b1, W2AS, W2AD, H2, AS2, AD2);
    k_agg2_w<<<(N_NODES + 7) / 8, 256>>>(b2, wg, bg, batch);

    // tail MLP
    k_mma3<<<mma_grid(N_GRAPHS, 256), 256>>>(target, Wxt, bxt, XT,
                                             N_GRAPHS, 1280, 256, 1280, 256, 256, 0);
    k_concat<<<(N_GRAPHS * 512 + 255) / 256, 256>>>();
    k_mma3<<<mma_grid(N_GRAPHS, 1024), 256>>>(XC, Wf1, bf1, X1,
                                              N_GRAPHS, 512, 1024, 512, 1024, 1024, 1);
    k_mma3<<<mma_grid(N_GRAPHS, 256), 256>>>(X1, Wf2, bf2, X2,
                                             N_GRAPHS, 1024, 256, 1024, 256, 256, 1);
    k_out<<<N_GRAPHS, 32>>>(Wo, bo, out);
}

// round 13
// speedup vs baseline: 1.0794x; 1.0794x over previous
#include <cuda_runtime.h>
#include <math.h>
#include <stdint.h>

#define N_NODES 100000
#define N_EDGES 400000
#define E_TOT   500000
#define N_GRAPHS 2048
#define F_IN 78
#define H1N 10
#define C1  780      // 10*78
#define C1P 800      // padded: 10 heads * 80
#define OUT2 128
#define NB_SCAN 98   // ceil(100000/1024)

// ---------------- scratch (device globals; no allocation allowed) -----------
__device__ __align__(16) float g_XAGG[(N_NODES + 32) * C1P]; // pitch-80/head, tf32-rounded
__device__ __align__(16) float g_H1O[N_NODES * C1 + 32 * C1]; // tf32-rounded elu(gat1)
__device__ __align__(16) float g_H2[N_NODES * OUT2];
__device__ float g_ASD1[N_NODES * 2 * H1N];
__device__ float g_AS2[N_NODES], g_AD2[N_NODES];
__device__ int   g_DEG[N_NODES], g_INCL[N_NODES], g_BSUM[128], g_BOFF[128];
__device__ int   g_OFF[N_NODES + 1], g_CUR[N_NODES], g_CSRC[E_TOT];
__device__ float g_WATT[F_IN * 2 * H1N];
__device__ __align__(16) float g_W1P[F_IN * C1P];   // W1 re-laid pitch 80/head, tf32-rounded
__device__ __align__(16) float g_W2P[C1 * OUT2];    // W2 tf32-rounded
__device__ float g_W2AS[C1], g_W2AD[C1];
__device__ float g_HSUM[N_GRAPHS * OUT2], g_HMAX[N_GRAPHS * OUT2];
__device__ __align__(16) float g_XT[N_GRAPHS * 256];
__device__ __align__(16) float g_XC[N_GRAPHS * 512];
__device__ __align__(16) float g_X1[N_GRAPHS * 1024];
__device__ __align__(16) float g_X2[N_GRAPHS * 256];

// ---------------- helpers ----------------------------------------------------
__device__ __forceinline__ uint32_t f2tf32(float v) {
    uint32_t u;
    asm("cvt.rna.tf32.f32 %0, %1;" : "=r"(u) : "f"(v));
    return u;
}
__device__ __forceinline__ float rtf(float v) { return __uint_as_float(f2tf32(v)); }
__device__ __forceinline__ void cp16n(void* dst, const float* src, int nbytes) {
    uint32_t d = (uint32_t)__cvta_generic_to_shared(dst);
    asm volatile("cp.async.cg.shared.global [%0], [%1], 16, %2;\n" :: "r"(d), "l"(src), "r"(nbytes));
}
#define MMA_TF32(ACC, A0, A1, A2, A3, B0, B1)                                   \
    asm volatile(                                                               \
        "mma.sync.aligned.m16n8k8.row.col.f32.tf32.tf32.f32 "                   \
        "{%0,%1,%2,%3}, {%4,%5,%6,%7}, {%8,%9}, {%0,%1,%2,%3};\n"               \
        : "+f"(ACC[0]), "+f"(ACC[1]), "+f"(ACC[2]), "+f"(ACC[3])                \
        : "r"(A0), "r"(A1), "r"(A2), "r"(A3), "r"(B0), "r"(B1))

// ---------------- CSR build -----------------------------------------------
__global__ void k_zero() {   // also inits DEG (self-loop)
    int i = blockIdx.x * blockDim.x + threadIdx.x;
    if (i < N_GRAPHS * OUT2) { g_HSUM[i] = 0.f; g_HMAX[i] = 0.f; }
    if (i < N_NODES) { g_AS2[i] = 0.f; g_AD2[i] = 0.f; g_DEG[i] = 1; }
}
__global__ void k_hist(const int* __restrict__ ei) {
    int e = blockIdx.x * blockDim.x + threadIdx.x;
    if (e < N_EDGES) atomicAdd(&g_DEG[ei[N_EDGES + e]], 1);
}
__global__ void k_scan1() {
    __shared__ int sw[32];
    int i = blockIdx.x * 1024 + threadIdx.x;
    int v = (i < N_NODES) ? g_DEG[i] : 0;
    int lane = threadIdx.x & 31, w = threadIdx.x >> 5;
    int x = v;
#pragma unroll
    for (int o = 1; o < 32; o <<= 1) {
        int y = __shfl_up_sync(0xffffffffu, x, o);
        if (lane >= o) x += y;
    }
    if (lane == 31) sw[w] = x;
    __syncthreads();
    if (w == 0) {
        int s = sw[lane];
#pragma unroll
        for (int o = 1; o < 32; o <<= 1) {
            int y = __shfl_up_sync(0xffffffffu, s, o);
            if (lane >= o) s += y;
        }
        sw[lane] = s;
    }
    __syncthreads();
    if (w > 0) x += sw[w - 1];
    if (i < N_NODES) g_INCL[i] = x;
    if (threadIdx.x == 1023) g_BSUM[blockIdx.x] = x;
}
__global__ void k_scan2() {
    __shared__ int sw[4];
    int t = threadIdx.x;
    int v = (t < NB_SCAN) ? g_BSUM[t] : 0;
    int lane = t & 31, w = t >> 5;
    int x = v;
#pragma unroll
    for (int o = 1; o < 32; o <<= 1) {
        int y = __shfl_up_sync(0xffffffffu, x, o);
        if (lane >= o) x += y;
    }
    if (lane == 31) sw[w] = x;
    __syncthreads();
    int add = 0;
    for (int i = 0; i < w; i++) add += sw[i];
    x += add;
    if (t < NB_SCAN) g_BOFF[t] = x - v;
}
__global__ void k_scan3() {
    int i = blockIdx.x * blockDim.x + threadIdx.x;
    if (i < N_NODES) {
        int off = g_INCL[i] - g_DEG[i] + g_BOFF[i >> 10];
        g_OFF[i] = off;
        g_CUR[i] = off;
        if (i == 0) g_OFF[N_NODES] = E_TOT;
    }
}
__global__ void k_scatter(const int* __restrict__ ei) {
    int i = blockIdx.x * blockDim.x + threadIdx.x;
    if (i >= E_TOT) return;
    int s, d;
    if (i < N_EDGES) { s = ei[i]; d = ei[N_EDGES + i]; }
    else             { s = d = i - N_EDGES; }
    int pos = atomicAdd(&g_CUR[d], 1);
    g_CSRC[pos] = s;
}

// ---------------- weight prep ----------------------------------------------
__global__ void k_prep_att(const float* __restrict__ W1, const float* __restrict__ as,
                           const float* __restrict__ ad) {
    int i = blockIdx.x * blockDim.x + threadIdx.x;
    if (i >= F_IN * 2 * H1N) return;
    int k = i / (2 * H1N), j = i - k * (2 * H1N);
    const float* a = (j < H1N) ? (as + j * F_IN) : (ad + (j - H1N) * F_IN);
    int h = (j < H1N) ? j : j - H1N;
    float s = 0.f;
    for (int d = 0; d < F_IN; d++) s += W1[k * C1 + h * F_IN + d] * a[d];
    g_WATT[i] = s;
}
__global__ void k_prep_w1p(const float* __restrict__ W1) {
    int i = blockIdx.x * blockDim.x + threadIdx.x;
    if (i >= F_IN * C1) return;
    int k = i / C1, c = i - k * C1;
    int h = c / F_IN, d = c - h * F_IN;
    g_W1P[k * C1P + h * 80 + d] = rtf(W1[i]);
}
__global__ void k_prep_w2p(const float* __restrict__ W2) {
    int i = blockIdx.x * blockDim.x + threadIdx.x;
    if (i < C1 * OUT2) g_W2P[i] = rtf(W2[i]);
}
__global__ void k_prep2v(const float* __restrict__ W2, const float* __restrict__ as,
                         const float* __restrict__ ad) {
    int k = blockIdx.x * blockDim.x + threadIdx.x;
    if (k >= C1) return;
    float s = 0.f, t = 0.f;
    for (int d = 0; d < OUT2; d++) {
        float w = W2[k * OUT2 + d];
        s = fmaf(w, as[d], s);
        t = fmaf(w, ad[d], t);
    }
    g_W2AS[k] = s;
    g_W2AD[k] = t;
}

// ---------------- attention logits ------------------------------------------
__global__ void k_att1(const float* __restrict__ x) {
    __shared__ float sW[F_IN * 2 * H1N];
    __shared__ float sX[8 * F_IN];
    int tid = threadIdx.x, w = tid >> 5, lane = tid & 31;
    for (int i = tid; i < F_IN * 2 * H1N; i += 256) sW[i] = g_WATT[i];
    int n = blockIdx.x * 8 + w;
    if (n < N_NODES) {
        for (int d = lane; d < F_IN; d += 32) sX[w * F_IN + d] = x[(size_t)n * F_IN + d];
    }
    __syncthreads();
    if (n >= N_NODES || lane >= 2 * H1N) return;
    float s = 0.f;
    for (int d = 0; d < F_IN; d++)
        s = fmaf(sX[w * F_IN + d], sW[d * 2 * H1N + lane], s);
    g_ASD1[n * 2 * H1N + lane] = s;
}

// ---------------- layer 1: fused softmax + x-space aggregation (warp/node) --
__global__ void k_aggx_w(const float* __restrict__ x) {
    int n = blockIdx.x * 8 + (threadIdx.x >> 5);
    if (n >= N_NODES) return;
    int lane = threadIdx.x & 31;
    int p0 = g_OFF[n], p1 = g_OFF[n + 1];
    float adst = (lane < H1N) ? g_ASD1[n * 2 * H1N + H1N + lane] : 0.f;
    float m = -1e30f;
    for (int p = p0; p < p1; p++) {
        int s = g_CSRC[p];
        if (lane < H1N) {
            float e = g_ASD1[s * 2 * H1N + lane] + adst;
            e = e > 0.f ? e : 0.2f * e;
            m = fmaxf(m, e);
        }
    }
    float den = 0.f;
    for (int p = p0; p < p1; p++) {
        int s = g_CSRC[p];
        if (lane < H1N) {
            float e = g_ASD1[s * 2 * H1N + lane] + adst;
            e = e > 0.f ? e : 0.2f * e;
            den += expf(e - m);
        }
    }
    float rd = 1.f / (den + 1e-16f);
    float acc[H1N][3];
#pragma unroll
    for (int h = 0; h < H1N; h++) { acc[h][0] = 0.f; acc[h][1] = 0.f; acc[h][2] = 0.f; }
    for (int p = p0; p < p1; p++) {
        int s = g_CSRC[p];
        float al = 0.f;
        if (lane < H1N) {
            float e = g_ASD1[s * 2 * H1N + lane] + adst;
            e = e > 0.f ? e : 0.2f * e;
            al = expf(e - m) * rd;
        }
        const float* xr = &x[(size_t)s * F_IN];
        float xv0 = xr[lane];
        float xv1 = xr[32 + lane];
        float xv2 = (lane < F_IN - 64) ? xr[64 + lane] : 0.f;
#pragma unroll
        for (int h = 0; h < H1N; h++) {
            float a = __shfl_sync(0xffffffffu, al, h);
            acc[h][0] = fmaf(a, xv0, acc[h][0]);
            acc[h][1] = fmaf(a, xv1, acc[h][1]);
            acc[h][2] = fmaf(a, xv2, acc[h][2]);
        }
    }
    size_t base = (size_t)n * C1P;
#pragma unroll
    for (int h = 0; h < H1N; h++) {
        g_XAGG[base + h * 80 + lane] = rtf(acc[h][0]);
        g_XAGG[base + h * 80 + 32 + lane] = rtf(acc[h][1]);
        if (lane < F_IN - 64) g_XAGG[base + h * 80 + 64 + lane] = rtf(acc[h][2]);
    }
}

// ---------------- TF32 GEMM: 64x128 tile, 8 warps, cp.async 2-stage, batched -
// CONV: convert fp32->tf32 at fragment load (else inputs pre-rounded).
// ROUND_OUT: round C to tf32 at store (feeds another no-conv GEMM).
#define PAp 20
#define PBp 136
template <bool CONV, bool ROUND_OUT>
__global__ void __launch_bounds__(256) k_mma3(
    const float* __restrict__ A_, const float* __restrict__ B_,
    const float* __restrict__ bias_, float* __restrict__ C_,
    int M, int K, int N, int lda, int ldb, int ldC, int act,
    long long stA, long long stB, long long stBias, long long stC,
    const float* __restrict__ attS_, const float* __restrict__ attD_,
    long long stAtt, float* __restrict__ outAS, float* __restrict__ outAD) {
    __shared__ __align__(16) float sA[2][64 * PAp];
    __shared__ __align__(16) float sB[2][16 * PBp];
    const float* A = A_ + (long long)blockIdx.z * stA;
    const float* B = B_ + (long long)blockIdx.z * stB;
    const float* bias = bias_ ? bias_ + (long long)blockIdx.z * stBias : nullptr;
    float* C = C_ + (long long)blockIdx.z * stC;
    const float* attS = attS_ ? attS_ + (long long)blockIdx.z * stAtt : nullptr;
    const float* attD = attD_ ? attD_ + (long long)blockIdx.z * stAtt : nullptr;

    int t = threadIdx.x;
    int warp = t >> 5, lane = t & 31;
    int g = lane >> 2, tg = lane & 3;
    int wm = warp >> 2, wn = warp & 3;
    int r0 = blockIdx.x * 64;
    int c0 = blockIdx.y * 128;

    int arow = t >> 2, acol = (t & 3) * 4;
    const float* aptr = A + (size_t)(r0 + arow) * lda + acol;
    int brow[2], bcol[2];
#pragma unroll
    for (int i = 0; i < 2; i++) {
        int id = t + i * 256;
        brow[i] = id >> 5;
        bcol[i] = (id & 31) * 4;
    }

    int niter = (K + 15) / 16;
    {
        cp16n(&sA[0][arow * PAp + acol], aptr, 16);
#pragma unroll
        for (int i = 0; i < 2; i++) {
            const float* src = B + (size_t)brow[i] * ldb + c0 + bcol[i];
            int nb = 0;
            if (brow[i] < K) {
                int v = N - (c0 + bcol[i]);
                nb = v >= 4 ? 16 : (v > 0 ? v * 4 : 0);
            }
            if (nb == 0) src = B;
            cp16n(&sB[0][brow[i] * PBp + bcol[i]], src, nb);
        }
        asm volatile("cp.async.commit_group;\n");
    }

    float acc[2][4][4];
#pragma unroll
    for (int mi = 0; mi < 2; mi++)
#pragma unroll
        for (int ni = 0; ni < 4; ni++)
#pragma unroll
            for (int r = 0; r < 4; r++) acc[mi][ni][r] = 0.f;

    for (int it = 0; it < niter; it++) {
        if (it + 1 < niter) {
            int kt = (it + 1) * 16;
            int bufp = (it + 1) & 1;
            cp16n(&sA[bufp][arow * PAp + acol], aptr + kt, 16);
#pragma unroll
            for (int i = 0; i < 2; i++) {
                const float* src = B + (size_t)(kt + brow[i]) * ldb + c0 + bcol[i];
                int nb = 0;
                if (kt + brow[i] < K) {
                    int v = N - (c0 + bcol[i]);
                    nb = v >= 4 ? 16 : (v > 0 ? v * 4 : 0);
                }
                if (nb == 0) src = B;
                cp16n(&sB[bufp][brow[i] * PBp + bcol[i]], src, nb);
            }
            asm volatile("cp.async.commit_group;\n");
            asm volatile("cp.async.wait_group 1;\n");
        } else {
            asm volatile("cp.async.wait_group 0;\n");
        }
        __syncthreads();
        int cb = it & 1;
#pragma unroll
        for (int kk = 0; kk < 16; kk += 8) {
            uint32_t af[2][4];
#pragma unroll
            for (int mi = 0; mi < 2; mi++) {
                int br = wm * 32 + mi * 16;
                if (CONV) {
                    af[mi][0] = f2tf32(sA[cb][(br + g) * PAp + kk + tg]);
                    af[mi][1] = f2tf32(sA[cb][(br + g + 8) * PAp + kk + tg]);
                    af[mi][2] = f2tf32(sA[cb][(br + g) * PAp + kk + tg + 4]);
                    af[mi][3] = f2tf32(sA[cb][(br + g + 8) * PAp + kk + tg + 4]);
                } else {
                    af[mi][0] = __float_as_uint(sA[cb][(br + g) * PAp + kk + tg]);
                    af[mi][1] = __float_as_uint(sA[cb][(br + g + 8) * PAp + kk + tg]);
                    af[mi][2] = __float_as_uint(sA[cb][(br + g) * PAp + kk + tg + 4]);
                    af[mi][3] = __float_as_uint(sA[cb][(br + g + 8) * PAp + kk + tg + 4]);
                }
            }
#pragma unroll
            for (int ni = 0; ni < 4; ni++) {
                int bc = wn * 32 + ni * 8 + g;
                uint32_t b0, bb;
                if (CONV) {
                    b0 = f2tf32(sB[cb][(kk + tg) * PBp + bc]);
                    bb = f2tf32(sB[cb][(kk + tg + 4) * PBp + bc]);
                } else {
                    b0 = __float_as_uint(sB[cb][(kk + tg) * PBp + bc]);
                    bb = __float_as_uint(sB[cb][(kk + tg + 4) * PBp + bc]);
                }
                MMA_TF32(acc[0][ni], af[0][0], af[0][1], af[0][2], af[0][3], b0, bb);
                MMA_TF32(acc[1][ni], af[1][0], af[1][1], af[1][2], af[1][3], b0, bb);
            }
        }
        __syncthreads();
    }
    // epilogue
#pragma unroll
    for (int mi = 0; mi < 2; mi++) {
#pragma unroll
        for (int half = 0; half < 2; half++) {
            int row = r0 + wm * 32 + mi * 16 + g + half * 8;
            float ps = 0.f, pd = 0.f;
#pragma unroll
            for (int ni = 0; ni < 4; ni++) {
                int col = c0 + wn * 32 + ni * 8 + tg * 2;
#pragma unroll
                for (int q = 0; q < 2; q++) {
                    if (row < M && col + q < N) {
                        float v = acc[mi][ni][half * 2 + q] + (bias ? bias[col + q] : 0.f);
                        if (act == 1) v = fmaxf(v, 0.f);
                        else if (act == 2) v = v > 0.f ? v : expm1f(v);
                        if (attS) {
                            ps = fmaf(v, attS[col + q], ps);
                            pd = fmaf(v, attD[col + q], pd);
                        }
                        if (ROUND_OUT) v = rtf(v);
                        C[(size_t)row * ldC + col + q] = v;
                    }
                }
            }
            if (attS) {
                ps += __shfl_xor_sync(0xffffffffu, ps, 1);
                ps += __shfl_xor_sync(0xffffffffu, ps, 2);
                pd += __shfl_xor_sync(0xffffffffu, pd, 1);
                pd += __shfl_xor_sync(0xffffffffu, pd, 2);
                if (tg == 0 && row < M) {
                    atomicAdd(&outAS[row], ps);
                    atomicAdd(&outAD[row], pd);
                }
            }
        }
    }
}

// ---------------- layer 2: fused softmax + aggregation + readout ------------
__global__ void k_agg2_w(const float* __restrict__ b2, const float* __restrict__ wg,
                         const float* __restrict__ bg, const int* __restrict__ batch) {
    int n = blockIdx.x * 8 + (threadIdx.x >> 5);
    if (n >= N_NODES) return;
    int lane = threadIdx.x & 31;
    int p0 = g_OFF[n], p1 = g_OFF[n + 1];
    float adst = g_AD2[n];
    float m = -1e30f;
    for (int p = p0; p < p1; p++) {
        float e = g_AS2[g_CSRC[p]] + adst;
        e = e > 0.f ? e : 0.2f * e;
        m = fmaxf(m, e);
    }
    float den = 0.f;
    for (int p = p0; p < p1; p++) {
        float e = g_AS2[g_CSRC[p]] + adst;
        e = e > 0.f ? e : 0.2f * e;
        den += expf(e - m);
    }
    float rd = 1.f / (den + 1e-16f);
    float a0 = 0.f, a1 = 0.f, a2 = 0.f, a3 = 0.f;
    for (int p = p0; p < p1; p++) {
        int s = g_CSRC[p];
        float e = g_AS2[s] + adst;
        e = e > 0.f ? e : 0.2f * e;
        float al = expf(e - m) * rd;
        const float* hr = &g_H2[(size_t)s * OUT2];
        a0 = fmaf(al, hr[lane], a0);
        a1 = fmaf(al, hr[32 + lane], a1);
        a2 = fmaf(al, hr[64 + lane], a2);
        a3 = fmaf(al, hr[96 + lane], a3);
    }
    float v0 = fmaxf(a0 + b2[lane], 0.f);
    float v1 = fmaxf(a1 + b2[32 + lane], 0.f);
    float v2 = fmaxf(a2 + b2[64 + lane], 0.f);
    float v3 = fmaxf(a3 + b2[96 + lane], 0.f);
    float gp = v0 * wg[lane] + v1 * wg[32 + lane] + v2 * wg[64 + lane] + v3 * wg[96 + lane];
#pragma unroll
    for (int o = 16; o > 0; o >>= 1) gp += __shfl_xor_sync(0xffffffffu, gp, o);
    float w = 1.f / (1.f + expf(-(gp + bg[0])));
    int gr = batch[n];
    float* hs = &g_HSUM[(size_t)gr * OUT2];
    float* hm = &g_HMAX[(size_t)gr * OUT2];
    atomicAdd(&hs[lane], v0 * w);
    atomicAdd(&hs[32 + lane], v1 * w);
    atomicAdd(&hs[64 + lane], v2 * w);
    atomicAdd(&hs[96 + lane], v3 * w);
    atomicMax((int*)&hm[lane], __float_as_int(v0));
    atomicMax((int*)&hm[32 + lane], __float_as_int(v1));
    atomicMax((int*)&hm[64 + lane], __float_as_int(v2));
    atomicMax((int*)&hm[96 + lane], __float_as_int(v3));
}

// ---------------- tail ------------------------------------------------------
__global__ void k_concat() {
    int i = blockIdx.x * blockDim.x + threadIdx.x;
    if (i >= N_GRAPHS * 512) return;
    int g = i / 512, c = i - g * 512;
    float v;
    if (c < 128)      v = g_HSUM[g * 128 + c];
    else if (c < 256) v = g_HMAX[g * 128 + (c - 128)];
    else              v = g_XT[g * 256 + (c - 256)];
    g_XC[i] = v;
}
__global__ void k_out(const float* __restrict__ Wo, const float* __restrict__ bo,
                      float* __restrict__ out) {
    int g = blockIdx.x, lane = threadIdx.x;
    float s = 0.f;
    for (int k = lane; k < 256; k += 32) s += g_X2[g * 256 + k] * Wo[k];
#pragma unroll
    for (int o = 16; o > 0; o >>= 1) s += __shfl_down_sync(0xffffffffu, s, o);
    if (lane == 0) out[g] = s + bo[0];
}

// ---------------- host ------------------------------------------------------
static inline dim3 mma_grid(int M, int N, int Z = 1) {
    return dim3((M + 63) / 64, (N + 127) / 128, Z);
}

extern "C" void kernel_launch(void* const* d_in, const int* in_sizes, int n_in,
                              void* d_out, int out_size) {
    const float* x      = (const float*)d_in[0];
    const int*   ei     = (const int*)d_in[1];
    const int*   batch  = (const int*)d_in[2];
    const float* target = (const float*)d_in[3];
    const float* W1  = (const float*)d_in[4];
    const float* as1 = (const float*)d_in[5];
    const float* ad1 = (const float*)d_in[6];
    const float* b1  = (const float*)d_in[7];
    const float* W2  = (const float*)d_in[8];
    const float* as2 = (const float*)d_in[9];
    const float* ad2 = (const float*)d_in[10];
    const float* b2  = (const float*)d_in[11];
    const float* wg  = (const float*)d_in[12];
    const float* bg  = (const float*)d_in[13];
    const float* Wxt = (const float*)d_in[14];
    const float* bxt = (const float*)d_in[15];
    const float* Wf1 = (const float*)d_in[16];
    const float* bf1 = (const float*)d_in[17];
    const float* Wf2 = (const float*)d_in[18];
    const float* bf2 = (const float*)d_in[19];
    const float* Wo  = (const float*)d_in[20];
    const float* bo  = (const float*)d_in[21];
    float* out = (float*)d_out;

    float *XAGG, *H1O, *H2, *W1P, *W2P, *W2AS, *W2AD, *AS2, *AD2, *XT, *XC, *X1, *X2;
    cudaGetSymbolAddress((void**)&XAGG, g_XAGG);
    cudaGetSymbolAddress((void**)&H1O, g_H1O);
    cudaGetSymbolAddress((void**)&H2,  g_H2);
    cudaGetSymbolAddress((void**)&W1P, g_W1P);
    cudaGetSymbolAddress((void**)&W2P, g_W2P);
    cudaGetSymbolAddress((void**)&W2AS, g_W2AS);
    cudaGetSymbolAddress((void**)&W2AD, g_W2AD);
    cudaGetSymbolAddress((void**)&AS2, g_AS2);
    cudaGetSymbolAddress((void**)&AD2, g_AD2);
    cudaGetSymbolAddress((void**)&XT,  g_XT);
    cudaGetSymbolAddress((void**)&XC,  g_XC);
    cudaGetSymbolAddress((void**)&X1,  g_X1);
    cudaGetSymbolAddress((void**)&X2,  g_X2);

    // CSR build + zero accumulators (k_zero also sets DEG=1)
    k_zero<<<(N_GRAPHS * OUT2 + 255) / 256, 256>>>();
    k_hist<<<(N_EDGES + 255) / 256, 256>>>(ei);
    k_scan1<<<NB_SCAN, 1024>>>();
    k_scan2<<<1, 128>>>();
    k_scan3<<<(N_NODES + 255) / 256, 256>>>();
    k_scatter<<<(E_TOT + 255) / 256, 256>>>(ei);

    // weight prep (tf32 pre-rounded copies for no-conv GEMMs)
    k_prep_att<<<(F_IN * 2 * H1N + 255) / 256, 256>>>(W1, as1, ad1);
    k_prep_w1p<<<(F_IN * C1 + 255) / 256, 256>>>(W1);
    k_prep_w2p<<<(C1 * OUT2 + 255) / 256, 256>>>(W2);
    k_prep2v<<<(C1 + 255) / 256, 256>>>(W2, as2, ad2);

    // layer 1: logits -> fused softmax+agg -> batched GEMM (+att2 fold), no-conv
    k_att1<<<(N_NODES + 7) / 8, 256>>>(x);
    k_aggx_w<<<(N_NODES + 7) / 8, 256>>>(x);
    k_mma3<false, true><<<mma_grid(N_NODES, F_IN, H1N), 256>>>(
        XAGG, W1P, b1, H1O, N_NODES, F_IN, F_IN, C1P, C1P, C1, 2,
        80, 80, F_IN, F_IN,
        W2AS, W2AD, F_IN, AS2, AD2);

    // layer 2: H2 = H1O @ W2P  [100000,780]x[780,128], no-conv
    k_mma3<false, false><<<mma_grid(N_NODES, OUT2), 256>>>(
        H1O, W2P, nullptr, H2, N_NODES, C1, OUT2, C1, OUT2, OUT2, 0,
        0, 0, 0, 0, nullptr, nullptr, 0, nullptr, nullptr);
    k_agg2_w<<<(N_NODES + 7) / 8, 256>>>(b2, wg, bg, batch);

    // tail MLP (small; keep load-time conversion)
    k_mma3<true, false><<<mma_grid(N_GRAPHS, 256), 256>>>(
        target, Wxt, bxt, XT, N_GRAPHS, 1280, 256, 1280, 256, 256, 0,
        0, 0, 0, 0, nullptr, nullptr, 0, nullptr, nullptr);
    k_concat<<<(N_GRAPHS * 512 + 255) / 256, 256>>>();
    k_mma3<true, false><<<mma_grid(N_GRAPHS, 1024), 256>>>(
        XC, Wf1, bf1, X1, N_GRAPHS, 512, 1024, 512, 1024, 1024, 1,
        0, 0, 0, 0, nullptr, nullptr, 0, nullptr, nullptr);
    k_mma3<true, false><<<mma_grid(N_GRAPHS, 256), 256>>>(
        X1, Wf2, bf2, X2, N_GRAPHS, 1024, 256, 1024, 256, 256, 1,
        0, 0, 0, 0, nullptr, nullptr, 0, nullptr, nullptr);
    k_out<<<N_GRAPHS, 32>>>(Wo, bo, out);
}

// round 14
// speedup vs baseline: 1.0859x; 1.0061x over previous
#include <cuda_runtime.h>
#include <math.h>
#include <stdint.h>

#define N_NODES 100000
#define N_EDGES 400000
#define E_TOT   500000
#define N_GRAPHS 2048
#define F_IN 78
#define H1N 10
#define C1  780      // 10*78
#define C1P 800      // padded: 10 heads * 80
#define OUT2 128
#define NB_SCAN 98   // ceil(100000/1024)

// ---------------- scratch (device globals; no allocation allowed) -----------
__device__ __align__(16) float g_XAGG[(N_NODES + 32) * C1P]; // pitch-80/head, tf32-rounded
__device__ __align__(16) float g_H1O[N_NODES * C1 + 32 * C1]; // tf32-rounded elu(gat1)
__device__ __align__(16) float g_H2[N_NODES * OUT2];
__device__ float g_ASD1[N_NODES * 2 * H1N];
__device__ float g_AS2[N_NODES], g_AD2[N_NODES];
__device__ int   g_DEG[N_NODES], g_INCL[N_NODES], g_BSUM[128], g_BOFF[128];
__device__ int   g_OFF[N_NODES + 1], g_CUR[N_NODES], g_CSRC[E_TOT];
__device__ float g_WATT[F_IN * 2 * H1N];
__device__ __align__(16) float g_W1P[F_IN * C1P];   // W1 re-laid pitch 80/head, tf32-rounded
__device__ __align__(16) float g_W2P[C1 * OUT2];    // W2 tf32-rounded
__device__ float g_W2AS[C1], g_W2AD[C1];
__device__ float g_HSUM[N_GRAPHS * OUT2], g_HMAX[N_GRAPHS * OUT2];
__device__ __align__(16) float g_XT[N_GRAPHS * 256];
__device__ __align__(16) float g_XC[N_GRAPHS * 512];
__device__ __align__(16) float g_X1[N_GRAPHS * 1024];
__device__ __align__(16) float g_X2[N_GRAPHS * 256];

// ---------------- helpers ----------------------------------------------------
__device__ __forceinline__ uint32_t f2tf32(float v) {
    uint32_t u;
    asm("cvt.rna.tf32.f32 %0, %1;" : "=r"(u) : "f"(v));
    return u;
}
__device__ __forceinline__ float rtf(float v) { return __uint_as_float(f2tf32(v)); }
__device__ __forceinline__ void cp16n(void* dst, const float* src, int nbytes) {
    uint32_t d = (uint32_t)__cvta_generic_to_shared(dst);
    asm volatile("cp.async.cg.shared.global [%0], [%1], 16, %2;\n" :: "r"(d), "l"(src), "r"(nbytes));
}
#define MMA_TF32(ACC, A0, A1, A2, A3, B0, B1)                                   \
    asm volatile(                                                               \
        "mma.sync.aligned.m16n8k8.row.col.f32.tf32.tf32.f32 "                   \
        "{%0,%1,%2,%3}, {%4,%5,%6,%7}, {%8,%9}, {%0,%1,%2,%3};\n"               \
        : "+f"(ACC[0]), "+f"(ACC[1]), "+f"(ACC[2]), "+f"(ACC[3])                \
        : "r"(A0), "r"(A1), "r"(A2), "r"(A3), "r"(B0), "r"(B1))

// ---------------- CSR build -----------------------------------------------
__global__ void k_zero() {   // also inits DEG (self-loop)
    int i = blockIdx.x * blockDim.x + threadIdx.x;
    if (i < N_GRAPHS * OUT2) { g_HSUM[i] = 0.f; g_HMAX[i] = 0.f; }
    if (i < N_NODES) { g_AS2[i] = 0.f; g_AD2[i] = 0.f; g_DEG[i] = 1; }
}
__global__ void k_hist(const int* __restrict__ ei) {
    int e = blockIdx.x * blockDim.x + threadIdx.x;
    if (e < N_EDGES) atomicAdd(&g_DEG[ei[N_EDGES + e]], 1);
}
__global__ void k_scan1() {
    __shared__ int sw[32];
    int i = blockIdx.x * 1024 + threadIdx.x;
    int v = (i < N_NODES) ? g_DEG[i] : 0;
    int lane = threadIdx.x & 31, w = threadIdx.x >> 5;
    int x = v;
#pragma unroll
    for (int o = 1; o < 32; o <<= 1) {
        int y = __shfl_up_sync(0xffffffffu, x, o);
        if (lane >= o) x += y;
    }
    if (lane == 31) sw[w] = x;
    __syncthreads();
    if (w == 0) {
        int s = sw[lane];
#pragma unroll
        for (int o = 1; o < 32; o <<= 1) {
            int y = __shfl_up_sync(0xffffffffu, s, o);
            if (lane >= o) s += y;
        }
        sw[lane] = s;
    }
    __syncthreads();
    if (w > 0) x += sw[w - 1];
    if (i < N_NODES) g_INCL[i] = x;
    if (threadIdx.x == 1023) g_BSUM[blockIdx.x] = x;
}
__global__ void k_scan2() {
    __shared__ int sw[4];
    int t = threadIdx.x;
    int v = (t < NB_SCAN) ? g_BSUM[t] : 0;
    int lane = t & 31, w = t >> 5;
    int x = v;
#pragma unroll
    for (int o = 1; o < 32; o <<= 1) {
        int y = __shfl_up_sync(0xffffffffu, x, o);
        if (lane >= o) x += y;
    }
    if (lane == 31) sw[w] = x;
    __syncthreads();
    int add = 0;
    for (int i = 0; i < w; i++) add += sw[i];
    x += add;
    if (t < NB_SCAN) g_BOFF[t] = x - v;
}
__global__ void k_scan3() {
    int i = blockIdx.x * blockDim.x + threadIdx.x;
    if (i < N_NODES) {
        int off = g_INCL[i] - g_DEG[i] + g_BOFF[i >> 10];
        g_OFF[i] = off;
        g_CUR[i] = off;
        if (i == 0) g_OFF[N_NODES] = E_TOT;
    }
}
__global__ void k_scatter(const int* __restrict__ ei) {
    int i = blockIdx.x * blockDim.x + threadIdx.x;
    if (i >= E_TOT) return;
    int s, d;
    if (i < N_EDGES) { s = ei[i]; d = ei[N_EDGES + i]; }
    else             { s = d = i - N_EDGES; }
    int pos = atomicAdd(&g_CUR[d], 1);
    g_CSRC[pos] = s;
}

// ---------------- weight prep ----------------------------------------------
__global__ void k_prep_att(const float* __restrict__ W1, const float* __restrict__ as,
                           const float* __restrict__ ad) {
    int i = blockIdx.x * blockDim.x + threadIdx.x;
    if (i >= F_IN * 2 * H1N) return;
    int k = i / (2 * H1N), j = i - k * (2 * H1N);
    const float* a = (j < H1N) ? (as + j * F_IN) : (ad + (j - H1N) * F_IN);
    int h = (j < H1N) ? j : j - H1N;
    float s = 0.f;
    for (int d = 0; d < F_IN; d++) s += W1[k * C1 + h * F_IN + d] * a[d];
    g_WATT[i] = s;
}
__global__ void k_prep_w1p(const float* __restrict__ W1) {
    int i = blockIdx.x * blockDim.x + threadIdx.x;
    if (i >= F_IN * C1) return;
    int k = i / C1, c = i - k * C1;
    int h = c / F_IN, d = c - h * F_IN;
    g_W1P[k * C1P + h * 80 + d] = rtf(W1[i]);
}
__global__ void k_prep_w2p(const float* __restrict__ W2) {
    int i = blockIdx.x * blockDim.x + threadIdx.x;
    if (i < C1 * OUT2) g_W2P[i] = rtf(W2[i]);
}
__global__ void k_prep2v(const float* __restrict__ W2, const float* __restrict__ as,
                         const float* __restrict__ ad) {
    int k = blockIdx.x * blockDim.x + threadIdx.x;
    if (k >= C1) return;
    float s = 0.f, t = 0.f;
    for (int d = 0; d < OUT2; d++) {
        float w = W2[k * OUT2 + d];
        s = fmaf(w, as[d], s);
        t = fmaf(w, ad[d], t);
    }
    g_W2AS[k] = s;
    g_W2AD[k] = t;
}

// ---------------- attention logits ------------------------------------------
__global__ void k_att1(const float* __restrict__ x) {
    __shared__ float sW[F_IN * 2 * H1N];
    __shared__ float sX[8 * F_IN];
    int tid = threadIdx.x, w = tid >> 5, lane = tid & 31;
    for (int i = tid; i < F_IN * 2 * H1N; i += 256) sW[i] = g_WATT[i];
    int n = blockIdx.x * 8 + w;
    if (n < N_NODES) {
        for (int d = lane; d < F_IN; d += 32) sX[w * F_IN + d] = x[(size_t)n * F_IN + d];
    }
    __syncthreads();
    if (n >= N_NODES || lane >= 2 * H1N) return;
    float s = 0.f;
    for (int d = 0; d < F_IN; d++)
        s = fmaf(sX[w * F_IN + d], sW[d * 2 * H1N + lane], s);
    g_ASD1[n * 2 * H1N + lane] = s;
}

// ---------------- layer 1: fused softmax + x-space aggregation (warp/node) --
__global__ void k_aggx_w(const float* __restrict__ x) {
    int n = blockIdx.x * 8 + (threadIdx.x >> 5);
    if (n >= N_NODES) return;
    int lane = threadIdx.x & 31;
    int p0 = g_OFF[n], p1 = g_OFF[n + 1];
    float adst = (lane < H1N) ? g_ASD1[n * 2 * H1N + H1N + lane] : 0.f;
    float m = -1e30f;
    for (int p = p0; p < p1; p++) {
        int s = g_CSRC[p];
        if (lane < H1N) {
            float e = g_ASD1[s * 2 * H1N + lane] + adst;
            e = e > 0.f ? e : 0.2f * e;
            m = fmaxf(m, e);
        }
    }
    float den = 0.f;
    for (int p = p0; p < p1; p++) {
        int s = g_CSRC[p];
        if (lane < H1N) {
            float e = g_ASD1[s * 2 * H1N + lane] + adst;
            e = e > 0.f ? e : 0.2f * e;
            den += expf(e - m);
        }
    }
    float rd = 1.f / (den + 1e-16f);
    float acc[H1N][3];
#pragma unroll
    for (int h = 0; h < H1N; h++) { acc[h][0] = 0.f; acc[h][1] = 0.f; acc[h][2] = 0.f; }
    for (int p = p0; p < p1; p++) {
        int s = g_CSRC[p];
        float al = 0.f;
        if (lane < H1N) {
            float e = g_ASD1[s * 2 * H1N + lane] + adst;
            e = e > 0.f ? e : 0.2f * e;
            al = expf(e - m) * rd;
        }
        const float* xr = &x[(size_t)s * F_IN];
        float xv0 = xr[lane];
        float xv1 = xr[32 + lane];
        float xv2 = (lane < F_IN - 64) ? xr[64 + lane] : 0.f;
#pragma unroll
        for (int h = 0; h < H1N; h++) {
            float a = __shfl_sync(0xffffffffu, al, h);
            acc[h][0] = fmaf(a, xv0, acc[h][0]);
            acc[h][1] = fmaf(a, xv1, acc[h][1]);
            acc[h][2] = fmaf(a, xv2, acc[h][2]);
        }
    }
    size_t base = (size_t)n * C1P;
#pragma unroll
    for (int h = 0; h < H1N; h++) {
        g_XAGG[base + h * 80 + lane] = rtf(acc[h][0]);
        g_XAGG[base + h * 80 + 32 + lane] = rtf(acc[h][1]);
        if (lane < F_IN - 64) g_XAGG[base + h * 80 + 64 + lane] = rtf(acc[h][2]);
    }
}

// ---------------- TF32 GEMM: 64x128 tile, 8 warps, cp.async 3-stage, batched -
// CONV: convert fp32->tf32 at fragment load (else inputs pre-rounded).
// ROUND_OUT: round C to tf32 at store (feeds another no-conv GEMM).
#define PAp 20
#define PBp 136
template <bool CONV, bool ROUND_OUT>
__global__ void __launch_bounds__(256) k_mma3(
    const float* __restrict__ A_, const float* __restrict__ B_,
    const float* __restrict__ bias_, float* __restrict__ C_,
    int M, int K, int N, int lda, int ldb, int ldC, int act,
    long long stA, long long stB, long long stBias, long long stC,
    const float* __restrict__ attS_, const float* __restrict__ attD_,
    long long stAtt, float* __restrict__ outAS, float* __restrict__ outAD) {
    __shared__ __align__(16) float sA[3][64 * PAp];
    __shared__ __align__(16) float sB[3][16 * PBp];
    const float* A = A_ + (long long)blockIdx.z * stA;
    const float* B = B_ + (long long)blockIdx.z * stB;
    const float* bias = bias_ ? bias_ + (long long)blockIdx.z * stBias : nullptr;
    float* C = C_ + (long long)blockIdx.z * stC;
    const float* attS = attS_ ? attS_ + (long long)blockIdx.z * stAtt : nullptr;
    const float* attD = attD_ ? attD_ + (long long)blockIdx.z * stAtt : nullptr;

    int t = threadIdx.x;
    int warp = t >> 5, lane = t & 31;
    int g = lane >> 2, tg = lane & 3;
    int wm = warp >> 2, wn = warp & 3;
    int r0 = blockIdx.x * 64;
    int c0 = blockIdx.y * 128;

    int arow = t >> 2, acol = (t & 3) * 4;
    const float* aptr = A + (size_t)(r0 + arow) * lda + acol;
    int brow[2], bcol[2];
#pragma unroll
    for (int i = 0; i < 2; i++) {
        int id = t + i * 256;
        brow[i] = id >> 5;
        bcol[i] = (id & 31) * 4;
    }

    int niter = (K + 15) / 16;

    auto issue = [&](int s, int buf) {
        int kt = s * 16;
        cp16n(&sA[buf][arow * PAp + acol], aptr + kt, 16);
#pragma unroll
        for (int i = 0; i < 2; i++) {
            const float* src = B + (size_t)(kt + brow[i]) * ldb + c0 + bcol[i];
            int nb = 0;
            if (kt + brow[i] < K) {
                int v = N - (c0 + bcol[i]);
                nb = v >= 4 ? 16 : (v > 0 ? v * 4 : 0);
            }
            if (nb == 0) src = B;
            cp16n(&sB[buf][brow[i] * PBp + bcol[i]], src, nb);
        }
    };

    // prologue: stages 0, 1 (one commit group each; empty if beyond niter)
#pragma unroll
    for (int s = 0; s < 2; s++) {
        if (s < niter) issue(s, s);
        asm volatile("cp.async.commit_group;\n");
    }

    float acc[2][4][4];
#pragma unroll
    for (int mi = 0; mi < 2; mi++)
#pragma unroll
        for (int ni = 0; ni < 4; ni++)
#pragma unroll
            for (int r = 0; r < 4; r++) acc[mi][ni][r] = 0.f;

    int cb = 0, ib = 2;   // compute buffer, issue buffer (rotating mod 3)
    for (int it = 0; it < niter; it++) {
        if (it + 2 < niter) issue(it + 2, ib);
        asm volatile("cp.async.commit_group;\n");
        asm volatile("cp.async.wait_group 2;\n");   // stage `it` landed
        __syncthreads();
#pragma unroll
        for (int kk = 0; kk < 16; kk += 8) {
            uint32_t af[2][4];
#pragma unroll
            for (int mi = 0; mi < 2; mi++) {
                int br = wm * 32 + mi * 16;
                if (CONV) {
                    af[mi][0] = f2tf32(sA[cb][(br + g) * PAp + kk + tg]);
                    af[mi][1] = f2tf32(sA[cb][(br + g + 8) * PAp + kk + tg]);
                    af[mi][2] = f2tf32(sA[cb][(br + g) * PAp + kk + tg + 4]);
                    af[mi][3] = f2tf32(sA[cb][(br + g + 8) * PAp + kk + tg + 4]);
                } else {
                    af[mi][0] = __float_as_uint(sA[cb][(br + g) * PAp + kk + tg]);
                    af[mi][1] = __float_as_uint(sA[cb][(br + g + 8) * PAp + kk + tg]);
                    af[mi][2] = __float_as_uint(sA[cb][(br + g) * PAp + kk + tg + 4]);
                    af[mi][3] = __float_as_uint(sA[cb][(br + g + 8) * PAp + kk + tg + 4]);
                }
            }
#pragma unroll
            for (int ni = 0; ni < 4; ni++) {
                int bc = wn * 32 + ni * 8 + g;
                uint32_t b0, bb;
                if (CONV) {
                    b0 = f2tf32(sB[cb][(kk + tg) * PBp + bc]);
                    bb = f2tf32(sB[cb][(kk + tg + 4) * PBp + bc]);
                } else {
                    b0 = __float_as_uint(sB[cb][(kk + tg) * PBp + bc]);
                    bb = __float_as_uint(sB[cb][(kk + tg + 4) * PBp + bc]);
                }
                MMA_TF32(acc[0][ni], af[0][0], af[0][1], af[0][2], af[0][3], b0, bb);
                MMA_TF32(acc[1][ni], af[1][0], af[1][1], af[1][2], af[1][3], b0, bb);
            }
        }
        __syncthreads();
        cb = (cb == 2) ? 0 : cb + 1;
        ib = (ib == 2) ? 0 : ib + 1;
    }
    // epilogue
#pragma unroll
    for (int mi = 0; mi < 2; mi++) {
#pragma unroll
        for (int half = 0; half < 2; half++) {
            int row = r0 + wm * 32 + mi * 16 + g + half * 8;
            float ps = 0.f, pd = 0.f;
#pragma unroll
            for (int ni = 0; ni < 4; ni++) {
                int col = c0 + wn * 32 + ni * 8 + tg * 2;
#pragma unroll
                for (int q = 0; q < 2; q++) {
                    if (row < M && col + q < N) {
                        float v = acc[mi][ni][half * 2 + q] + (bias ? bias[col + q] : 0.f);
                        if (act == 1) v = fmaxf(v, 0.f);
                        else if (act == 2) v = v > 0.f ? v : expm1f(v);
                        if (attS) {
                            ps = fmaf(v, attS[col + q], ps);
                            pd = fmaf(v, attD[col + q], pd);
                        }
                        if (ROUND_OUT) v = rtf(v);
                        C[(size_t)row * ldC + col + q] = v;
                    }
                }
            }
            if (attS) {
                ps += __shfl_xor_sync(0xffffffffu, ps, 1);
                ps += __shfl_xor_sync(0xffffffffu, ps, 2);
                pd += __shfl_xor_sync(0xffffffffu, pd, 1);
                pd += __shfl_xor_sync(0xffffffffu, pd, 2);
                if (tg == 0 && row < M) {
                    atomicAdd(&outAS[row], ps);
                    atomicAdd(&outAD[row], pd);
                }
            }
        }
    }
}

// ---------------- layer 2: fused softmax + aggregation + readout ------------
__global__ void k_agg2_w(const float* __restrict__ b2, const float* __restrict__ wg,
                         const float* __restrict__ bg, const int* __restrict__ batch) {
    int n = blockIdx.x * 8 + (threadIdx.x >> 5);
    if (n >= N_NODES) return;
    int lane = threadIdx.x & 31;
    int p0 = g_OFF[n], p1 = g_OFF[n + 1];
    float adst = g_AD2[n];
    float m = -1e30f;
    for (int p = p0; p < p1; p++) {
        float e = g_AS2[g_CSRC[p]] + adst;
        e = e > 0.f ? e : 0.2f * e;
        m = fmaxf(m, e);
    }
    float den = 0.f;
    for (int p = p0; p < p1; p++) {
        float e = g_AS2[g_CSRC[p]] + adst;
        e = e > 0.f ? e : 0.2f * e;
        den += expf(e - m);
    }
    float rd = 1.f / (den + 1e-16f);
    float a0 = 0.f, a1 = 0.f, a2 = 0.f, a3 = 0.f;
    for (int p = p0; p < p1; p++) {
        int s = g_CSRC[p];
        float e = g_AS2[s] + adst;
        e = e > 0.f ? e : 0.2f * e;
        float al = expf(e - m) * rd;
        const float* hr = &g_H2[(size_t)s * OUT2];
        a0 = fmaf(al, hr[lane], a0);
        a1 = fmaf(al, hr[32 + lane], a1);
        a2 = fmaf(al, hr[64 + lane], a2);
        a3 = fmaf(al, hr[96 + lane], a3);
    }
    float v0 = fmaxf(a0 + b2[lane], 0.f);
    float v1 = fmaxf(a1 + b2[32 + lane], 0.f);
    float v2 = fmaxf(a2 + b2[64 + lane], 0.f);
    float v3 = fmaxf(a3 + b2[96 + lane], 0.f);
    float gp = v0 * wg[lane] + v1 * wg[32 + lane] + v2 * wg[64 + lane] + v3 * wg[96 + lane];
#pragma unroll
    for (int o = 16; o > 0; o >>= 1) gp += __shfl_xor_sync(0xffffffffu, gp, o);
    float w = 1.f / (1.f + expf(-(gp + bg[0])));
    int gr = batch[n];
    float* hs = &g_HSUM[(size_t)gr * OUT2];
    float* hm = &g_HMAX[(size_t)gr * OUT2];
    atomicAdd(&hs[lane], v0 * w);
    atomicAdd(&hs[32 + lane], v1 * w);
    atomicAdd(&hs[64 + lane], v2 * w);
    atomicAdd(&hs[96 + lane], v3 * w);
    atomicMax((int*)&hm[lane], __float_as_int(v0));
    atomicMax((int*)&hm[32 + lane], __float_as_int(v1));
    atomicMax((int*)&hm[64 + lane], __float_as_int(v2));
    atomicMax((int*)&hm[96 + lane], __float_as_int(v3));
}

// ---------------- tail ------------------------------------------------------
__global__ void k_concat() {
    int i = blockIdx.x * blockDim.x + threadIdx.x;
    if (i >= N_GRAPHS * 512) return;
    int g = i / 512, c = i - g * 512;
    float v;
    if (c < 128)      v = g_HSUM[g * 128 + c];
    else if (c < 256) v = g_HMAX[g * 128 + (c - 128)];
    else              v = g_XT[g * 256 + (c - 256)];
    g_XC[i] = v;
}
__global__ void k_out(const float* __restrict__ Wo, const float* __restrict__ bo,
                      float* __restrict__ out) {
    int g = blockIdx.x, lane = threadIdx.x;
    float s = 0.f;
    for (int k = lane; k < 256; k += 32) s += g_X2[g * 256 + k] * Wo[k];
#pragma unroll
    for (int o = 16; o > 0; o >>= 1) s += __shfl_down_sync(0xffffffffu, s, o);
    if (lane == 0) out[g] = s + bo[0];
}

// ---------------- host ------------------------------------------------------
static inline dim3 mma_grid(int M, int N, int Z = 1) {
    return dim3((M + 63) / 64, (N + 127) / 128, Z);
}

extern "C" void kernel_launch(void* const* d_in, const int* in_sizes, int n_in,
                              void* d_out, int out_size) {
    const float* x      = (const float*)d_in[0];
    const int*   ei     = (const int*)d_in[1];
    const int*   batch  = (const int*)d_in[2];
    const float* target = (const float*)d_in[3];
    const float* W1  = (const float*)d_in[4];
    const float* as1 = (const float*)d_in[5];
    const float* ad1 = (const float*)d_in[6];
    const float* b1  = (const float*)d_in[7];
    const float* W2  = (const float*)d_in[8];
    const float* as2 = (const float*)d_in[9];
    const float* ad2 = (const float*)d_in[10];
    const float* b2  = (const float*)d_in[11];
    const float* wg  = (const float*)d_in[12];
    const float* bg  = (const float*)d_in[13];
    const float* Wxt = (const float*)d_in[14];
    const float* bxt = (const float*)d_in[15];
    const float* Wf1 = (const float*)d_in[16];
    const float* bf1 = (const float*)d_in[17];
    const float* Wf2 = (const float*)d_in[18];
    const float* bf2 = (const float*)d_in[19];
    const float* Wo  = (const float*)d_in[20];
    const float* bo  = (const float*)d_in[21];
    float* out = (float*)d_out;

    float *XAGG, *H1O, *H2, *W1P, *W2P, *W2AS, *W2AD, *AS2, *AD2, *XT, *XC, *X1, *X2;
    cudaGetSymbolAddress((void**)&XAGG, g_XAGG);
    cudaGetSymbolAddress((void**)&H1O, g_H1O);
    cudaGetSymbolAddress((void**)&H2,  g_H2);
    cudaGetSymbolAddress((void**)&W1P, g_W1P);
    cudaGetSymbolAddress((void**)&W2P, g_W2P);
    cudaGetSymbolAddress((void**)&W2AS, g_W2AS);
    cudaGetSymbolAddress((void**)&W2AD, g_W2AD);
    cudaGetSymbolAddress((void**)&AS2, g_AS2);
    cudaGetSymbolAddress((void**)&AD2, g_AD2);
    cudaGetSymbolAddress((void**)&XT,  g_XT);
    cudaGetSymbolAddress((void**)&XC,  g_XC);
    cudaGetSymbolAddress((void**)&X1,  g_X1);
    cudaGetSymbolAddress((void**)&X2,  g_X2);

    // CSR build + zero accumulators (k_zero also sets DEG=1)
    k_zero<<<(N_GRAPHS * OUT2 + 255) / 256, 256>>>();
    k_hist<<<(N_EDGES + 255) / 256, 256>>>(ei);
    k_scan1<<<NB_SCAN, 1024>>>();
    k_scan2<<<1, 128>>>();
    k_scan3<<<(N_NODES + 255) / 256, 256>>>();
    k_scatter<<<(E_TOT + 255) / 256, 256>>>(ei);

    // weight prep (tf32 pre-rounded copies for no-conv GEMMs)
    k_prep_att<<<(F_IN * 2 * H1N + 255) / 256, 256>>>(W1, as1, ad1);
    k_prep_w1p<<<(F_IN * C1 + 255) / 256, 256>>>(W1);
    k_prep_w2p<<<(C1 * OUT2 + 255) / 256, 256>>>(W2);
    k_prep2v<<<(C1 + 255) / 256, 256>>>(W2, as2, ad2);

    // layer 1: logits -> fused softmax+agg -> batched GEMM (+att2 fold), no-conv
    k_att1<<<(N_NODES + 7) / 8, 256>>>(x);
    k_aggx_w<<<(N_NODES + 7) / 8, 256>>>(x);
    k_mma3<false, true><<<mma_grid(N_NODES, F_IN, H1N), 256>>>(
        XAGG, W1P, b1, H1O, N_NODES, F_IN, F_IN, C1P, C1P, C1, 2,
        80, 80, F_IN, F_IN,
        W2AS, W2AD, F_IN, AS2, AD2);

    // layer 2: H2 = H1O @ W2P  [100000,780]x[780,128], no-conv
    k_mma3<false, false><<<mma_grid(N_NODES, OUT2), 256>>>(
        H1O, W2P, nullptr, H2, N_NODES, C1, OUT2, C1, OUT2, OUT2, 0,
        0, 0, 0, 0, nullptr, nullptr, 0, nullptr, nullptr);
    k_agg2_w<<<(N_NODES + 7) / 8, 256>>>(b2, wg, bg, batch);

    // tail MLP (small; keep load-time conversion)
    k_mma3<true, false><<<mma_grid(N_GRAPHS, 256), 256>>>(
        target, Wxt, bxt, XT, N_GRAPHS, 1280, 256, 1280, 256, 256, 0,
        0, 0, 0, 0, nullptr, nullptr, 0, nullptr, nullptr);
    k_concat<<<(N_GRAPHS * 512 + 255) / 256, 256>>>();
    k_mma3<true, false><<<mma_grid(N_GRAPHS, 1024), 256>>>(
        XC, Wf1, bf1, X1, N_GRAPHS, 512, 1024, 512, 1024, 1024, 1,
        0, 0, 0, 0, nullptr, nullptr, 0, nullptr, nullptr);
    k_mma3<true, false><<<mma_grid(N_GRAPHS, 256), 256>>>(
        X1, Wf2, bf2, X2, N_GRAPHS, 1024, 256, 1024, 256, 256, 1,
        0, 0, 0, 0, nullptr, nullptr, 0, nullptr, nullptr);
    k_out<<<N_GRAPHS, 32>>>(Wo, bo, out);
}

// round 15
// speedup vs baseline: 1.2871x; 1.1852x over previous
#include <cuda_runtime.h>
#include <cuda_fp16.h>
#include <math.h>
#include <stdint.h>

#define N_NODES 100000
#define N_EDGES 400000
#define E_TOT   500000
#define N_GRAPHS 2048
#define F_IN 78
#define H1N 10
#define C1  780      // 10*78
#define C1P 800      // padded: 10 heads * 80
#define H1OP 784     // H1O half pitch (16B aligned)
#define OUT2 128
#define NB_SCAN 98   // ceil(100000/1024)

// ---------------- scratch (device globals; no allocation allowed) -----------
__device__ __align__(16) __half g_XAGGH[(N_NODES + 64) * C1P];  // fp16, pitch 80/head
__device__ __align__(16) __half g_H1OH[(N_NODES + 64) * H1OP];  // fp16 elu(gat1)
__device__ __align__(16) float g_H2[N_NODES * OUT2];
__device__ float g_ASD1[N_NODES * 2 * H1N];
__device__ float g_AS2[N_NODES], g_AD2[N_NODES];
__device__ int   g_DEG[N_NODES], g_INCL[N_NODES], g_BSUM[128], g_BOFF[128];
__device__ int   g_OFF[N_NODES + 1], g_CUR[N_NODES], g_CSRC[E_TOT];
__device__ float g_WATT[F_IN * 2 * H1N];
__device__ __align__(16) __half g_W1TH[(H1N * 80 + 128) * 80]; // W1 transposed [h][n][k], pads zero
__device__ __align__(16) __half g_W2TH[OUT2 * H1OP];           // W2 transposed [n][k], pads zero
__device__ float g_W2AS[C1], g_W2AD[C1];
__device__ float g_HSUM[N_GRAPHS * OUT2], g_HMAX[N_GRAPHS * OUT2];
__device__ __align__(16) float g_XT[N_GRAPHS * 256];
__device__ __align__(16) float g_XC[N_GRAPHS * 512];
__device__ __align__(16) float g_X1[N_GRAPHS * 1024];
__device__ __align__(16) float g_X2[N_GRAPHS * 256];

// ---------------- helpers ----------------------------------------------------
__device__ __forceinline__ uint32_t f2tf32(float v) {
    uint32_t u;
    asm("cvt.rna.tf32.f32 %0, %1;" : "=r"(u) : "f"(v));
    return u;
}
__device__ __forceinline__ void cp16n(void* dst, const void* src, int nbytes) {
    uint32_t d = (uint32_t)__cvta_generic_to_shared(dst);
    asm volatile("cp.async.cg.shared.global [%0], [%1], 16, %2;\n" :: "r"(d), "l"(src), "r"(nbytes));
}
#define MMA_TF32(ACC, A0, A1, A2, A3, B0, B1)                                   \
    asm volatile(                                                               \
        "mma.sync.aligned.m16n8k8.row.col.f32.tf32.tf32.f32 "                   \
        "{%0,%1,%2,%3}, {%4,%5,%6,%7}, {%8,%9}, {%0,%1,%2,%3};\n"               \
        : "+f"(ACC[0]), "+f"(ACC[1]), "+f"(ACC[2]), "+f"(ACC[3])                \
        : "r"(A0), "r"(A1), "r"(A2), "r"(A3), "r"(B0), "r"(B1))
#define MMA_F16(ACC, A0, A1, A2, A3, B0, B1)                                    \
    asm volatile(                                                               \
        "mma.sync.aligned.m16n8k16.row.col.f32.f16.f16.f32 "                    \
        "{%0,%1,%2,%3}, {%4,%5,%6,%7}, {%8,%9}, {%0,%1,%2,%3};\n"               \
        : "+f"(ACC[0]), "+f"(ACC[1]), "+f"(ACC[2]), "+f"(ACC[3])                \
        : "r"(A0), "r"(A1), "r"(A2), "r"(A3), "r"(B0), "r"(B1))

// ---------------- CSR build -----------------------------------------------
__global__ void k_zero() {   // also inits DEG (self-loop)
    int i = blockIdx.x * blockDim.x + threadIdx.x;
    if (i < N_GRAPHS * OUT2) { g_HSUM[i] = 0.f; g_HMAX[i] = 0.f; }
    if (i < N_NODES) { g_AS2[i] = 0.f; g_AD2[i] = 0.f; g_DEG[i] = 1; }
}
__global__ void k_hist(const int* __restrict__ ei) {
    int e = blockIdx.x * blockDim.x + threadIdx.x;
    if (e < N_EDGES) atomicAdd(&g_DEG[ei[N_EDGES + e]], 1);
}
__global__ void k_scan1() {
    __shared__ int sw[32];
    int i = blockIdx.x * 1024 + threadIdx.x;
    int v = (i < N_NODES) ? g_DEG[i] : 0;
    int lane = threadIdx.x & 31, w = threadIdx.x >> 5;
    int x = v;
#pragma unroll
    for (int o = 1; o < 32; o <<= 1) {
        int y = __shfl_up_sync(0xffffffffu, x, o);
        if (lane >= o) x += y;
    }
    if (lane == 31) sw[w] = x;
    __syncthreads();
    if (w == 0) {
        int s = sw[lane];
#pragma unroll
        for (int o = 1; o < 32; o <<= 1) {
            int y = __shfl_up_sync(0xffffffffu, s, o);
            if (lane >= o) s += y;
        }
        sw[lane] = s;
    }
    __syncthreads();
    if (w > 0) x += sw[w - 1];
    if (i < N_NODES) g_INCL[i] = x;
    if (threadIdx.x == 1023) g_BSUM[blockIdx.x] = x;
}
__global__ void k_scan2() {
    __shared__ int sw[4];
    int t = threadIdx.x;
    int v = (t < NB_SCAN) ? g_BSUM[t] : 0;
    int lane = t & 31, w = t >> 5;
    int x = v;
#pragma unroll
    for (int o = 1; o < 32; o <<= 1) {
        int y = __shfl_up_sync(0xffffffffu, x, o);
        if (lane >= o) x += y;
    }
    if (lane == 31) sw[w] = x;
    __syncthreads();
    int add = 0;
    for (int i = 0; i < w; i++) add += sw[i];
    x += add;
    if (t < NB_SCAN) g_BOFF[t] = x - v;
}
__global__ void k_scan3() {
    int i = blockIdx.x * blockDim.x + threadIdx.x;
    if (i < N_NODES) {
        int off = g_INCL[i] - g_DEG[i] + g_BOFF[i >> 10];
        g_OFF[i] = off;
        g_CUR[i] = off;
        if (i == 0) g_OFF[N_NODES] = E_TOT;
    }
}
__global__ void k_scatter(const int* __restrict__ ei) {
    int i = blockIdx.x * blockDim.x + threadIdx.x;
    if (i >= E_TOT) return;
    int s, d;
    if (i < N_EDGES) { s = ei[i]; d = ei[N_EDGES + i]; }
    else             { s = d = i - N_EDGES; }
    int pos = atomicAdd(&g_CUR[d], 1);
    g_CSRC[pos] = s;
}

// ---------------- weight prep ----------------------------------------------
__global__ void k_prep_att(const float* __restrict__ W1, const float* __restrict__ as,
                           const float* __restrict__ ad) {
    int i = blockIdx.x * blockDim.x + threadIdx.x;
    if (i >= F_IN * 2 * H1N) return;
    int k = i / (2 * H1N), j = i - k * (2 * H1N);
    const float* a = (j < H1N) ? (as + j * F_IN) : (ad + (j - H1N) * F_IN);
    int h = (j < H1N) ? j : j - H1N;
    float s = 0.f;
    for (int d = 0; d < F_IN; d++) s += W1[k * C1 + h * F_IN + d] * a[d];
    g_WATT[i] = s;
}
// W1 transposed to [h][n 80][k 80] half; pads never written (stay zero)
__global__ void k_prep_w1t(const float* __restrict__ W1) {
    int i = blockIdx.x * blockDim.x + threadIdx.x;
    if (i >= H1N * F_IN * F_IN) return;
    int h = i / (F_IN * F_IN), r = i - h * F_IN * F_IN;
    int n = r / F_IN, k = r - n * F_IN;
    g_W1TH[(h * 80 + n) * 80 + k] = __float2half(W1[k * C1 + h * F_IN + n]);
}
// W2 transposed to [n 128][k pitch 784] half
__global__ void k_prep_w2t(const float* __restrict__ W2) {
    int i = blockIdx.x * blockDim.x + threadIdx.x;
    if (i >= C1 * OUT2) return;
    int k = i >> 7, n = i & 127;
    g_W2TH[n * H1OP + k] = __float2half(W2[i]);
}
__global__ void k_prep2v(const float* __restrict__ W2, const float* __restrict__ as,
                         const float* __restrict__ ad) {
    int k = blockIdx.x * blockDim.x + threadIdx.x;
    if (k >= C1) return;
    float s = 0.f, t = 0.f;
    for (int d = 0; d < OUT2; d++) {
        float w = W2[k * OUT2 + d];
        s = fmaf(w, as[d], s);
        t = fmaf(w, ad[d], t);
    }
    g_W2AS[k] = s;
    g_W2AD[k] = t;
}

// ---------------- attention logits ------------------------------------------
__global__ void k_att1(const float* __restrict__ x) {
    __shared__ float sW[F_IN * 2 * H1N];
    __shared__ float sX[8 * F_IN];
    int tid = threadIdx.x, w = tid >> 5, lane = tid & 31;
    for (int i = tid; i < F_IN * 2 * H1N; i += 256) sW[i] = g_WATT[i];
    int n = blockIdx.x * 8 + w;
    if (n < N_NODES) {
        for (int d = lane; d < F_IN; d += 32) sX[w * F_IN + d] = x[(size_t)n * F_IN + d];
    }
    __syncthreads();
    if (n >= N_NODES || lane >= 2 * H1N) return;
    float s = 0.f;
    for (int d = 0; d < F_IN; d++)
        s = fmaf(sX[w * F_IN + d], sW[d * 2 * H1N + lane], s);
    g_ASD1[n * 2 * H1N + lane] = s;
}

// ---------------- layer 1: fused softmax + x-space aggregation (warp/node) --
__global__ void k_aggx_w(const float* __restrict__ x) {
    int n = blockIdx.x * 8 + (threadIdx.x >> 5);
    if (n >= N_NODES) return;
    int lane = threadIdx.x & 31;
    int p0 = g_OFF[n], p1 = g_OFF[n + 1];
    float adst = (lane < H1N) ? g_ASD1[n * 2 * H1N + H1N + lane] : 0.f;
    float m = -1e30f;
    for (int p = p0; p < p1; p++) {
        int s = g_CSRC[p];
        if (lane < H1N) {
            float e = g_ASD1[s * 2 * H1N + lane] + adst;
            e = e > 0.f ? e : 0.2f * e;
            m = fmaxf(m, e);
        }
    }
    float den = 0.f;
    for (int p = p0; p < p1; p++) {
        int s = g_CSRC[p];
        if (lane < H1N) {
            float e = g_ASD1[s * 2 * H1N + lane] + adst;
            e = e > 0.f ? e : 0.2f * e;
            den += expf(e - m);
        }
    }
    float rd = 1.f / (den + 1e-16f);
    float acc[H1N][3];
#pragma unroll
    for (int h = 0; h < H1N; h++) { acc[h][0] = 0.f; acc[h][1] = 0.f; acc[h][2] = 0.f; }
    for (int p = p0; p < p1; p++) {
        int s = g_CSRC[p];
        float al = 0.f;
        if (lane < H1N) {
            float e = g_ASD1[s * 2 * H1N + lane] + adst;
            e = e > 0.f ? e : 0.2f * e;
            al = expf(e - m) * rd;
        }
        const float* xr = &x[(size_t)s * F_IN];
        float xv0 = xr[lane];
        float xv1 = xr[32 + lane];
        float xv2 = (lane < F_IN - 64) ? xr[64 + lane] : 0.f;
#pragma unroll
        for (int h = 0; h < H1N; h++) {
            float a = __shfl_sync(0xffffffffu, al, h);
            acc[h][0] = fmaf(a, xv0, acc[h][0]);
            acc[h][1] = fmaf(a, xv1, acc[h][1]);
            acc[h][2] = fmaf(a, xv2, acc[h][2]);
        }
    }
    size_t base = (size_t)n * C1P;
#pragma unroll
    for (int h = 0; h < H1N; h++) {
        g_XAGGH[base + h * 80 + lane] = __float2half(acc[h][0]);
        g_XAGGH[base + h * 80 + 32 + lane] = __float2half(acc[h][1]);
        if (lane < F_IN - 64) g_XAGGH[base + h * 80 + 64 + lane] = __float2half(acc[h][2]);
    }
}

// ---------------- FP16 GEMM: 64x128 tile, 8 warps, cp.async 3-stage, batched -
// A [M, lda] half row-major; B [n][k] half (transposed, ldb = k-pitch).
// B zero-filled beyond K rows / N cols; A pad reads are finite halves (x 0 = 0).
// OUT_HALF: store C as half; FOLD: accumulate attS/attD row-dots.
#define PAH 40   // A smem pitch (halves)
#define PBH 40   // B smem pitch (halves)
template <bool OUT_HALF, bool FOLD>
__global__ void __launch_bounds__(256) k_mma_h(
    const __half* __restrict__ A_, const __half* __restrict__ B_,
    const float* __restrict__ bias_, void* __restrict__ C_,
    int M, int K, int N, int lda, int ldb, int ldC, int act,
    long long stA, long long stB, long long stBias, long long stC,
    const float* __restrict__ attS_, const float* __restrict__ attD_,
    long long stAtt, float* __restrict__ outAS, float* __restrict__ outAD) {
    __shared__ __align__(16) __half sA[3][64 * PAH];
    __shared__ __align__(16) __half sB[3][128 * PBH];
    const __half* A = A_ + (long long)blockIdx.z * stA;
    const __half* B = B_ + (long long)blockIdx.z * stB;
    const float* bias = bias_ ? bias_ + (long long)blockIdx.z * stBias : nullptr;
    const float* attS = FOLD ? attS_ + (long long)blockIdx.z * stAtt : nullptr;
    const float* attD = FOLD ? attD_ + (long long)blockIdx.z * stAtt : nullptr;

    int t = threadIdx.x;
    int warp = t >> 5, lane = t & 31;
    int g = lane >> 2, tg = lane & 3;
    int wm = warp >> 2, wn = warp & 3;
    int r0 = blockIdx.x * 64;
    int c0 = blockIdx.y * 128;

    int niter = (K + 31) / 32;

    auto issue = [&](int s, int buf) {
        int kt = s * 32;
        // A: 64 rows x 32 halves, 1 chunk (16B = 8 halves) per thread
        {
            int row = t >> 2, koff = (t & 3) * 8;
            cp16n(&sA[buf][row * PAH + koff],
                  A + (size_t)(r0 + row) * lda + kt + koff, 16);
        }
        // B: 128 n-rows x 32 halves, 2 chunks per thread; zero-fill past K/N
#pragma unroll
        for (int i = 0; i < 2; i++) {
            int c = t + i * 256;
            int n = c >> 2, koff = (c & 3) * 8;
            const __half* src = B + (size_t)n * ldb + kt + koff;
            int nb = 0;
            if (c0 + n < N) {
                int rem = K - (kt + koff);
                nb = rem >= 8 ? 16 : (rem > 0 ? rem * 2 : 0);
            }
            if (nb == 0) src = B;
            cp16n(&sB[buf][n * PBH + koff], src, nb);
        }
    };

#pragma unroll
    for (int s = 0; s < 2; s++) {
        if (s < niter) issue(s, s);
        asm volatile("cp.async.commit_group;\n");
    }

    float acc[2][4][4];
#pragma unroll
    for (int mi = 0; mi < 2; mi++)
#pragma unroll
        for (int ni = 0; ni < 4; ni++)
#pragma unroll
            for (int r = 0; r < 4; r++) acc[mi][ni][r] = 0.f;

    int cb = 0, ib = 2;
    for (int it = 0; it < niter; it++) {
        if (it + 2 < niter) issue(it + 2, ib);
        asm volatile("cp.async.commit_group;\n");
        asm volatile("cp.async.wait_group 2;\n");
        __syncthreads();
#pragma unroll
        for (int kk = 0; kk < 32; kk += 16) {
            uint32_t af[2][4];
#pragma unroll
            for (int mi = 0; mi < 2; mi++) {
                int br = wm * 32 + mi * 16;
                const __half* a0 = &sA[cb][(br + g) * PAH + kk + 2 * tg];
                const __half* a1 = &sA[cb][(br + g + 8) * PAH + kk + 2 * tg];
                af[mi][0] = *(const uint32_t*)a0;
                af[mi][1] = *(const uint32_t*)a1;
                af[mi][2] = *(const uint32_t*)(a0 + 8);
                af[mi][3] = *(const uint32_t*)(a1 + 8);
            }
#pragma unroll
            for (int ni = 0; ni < 4; ni++) {
                int bc = wn * 32 + ni * 8 + g;
                const __half* b0 = &sB[cb][bc * PBH + kk + 2 * tg];
                uint32_t rb0 = *(const uint32_t*)b0;
                uint32_t rb1 = *(const uint32_t*)(b0 + 8);
                MMA_F16(acc[0][ni], af[0][0], af[0][1], af[0][2], af[0][3], rb0, rb1);
                MMA_F16(acc[1][ni], af[1][0], af[1][1], af[1][2], af[1][3], rb0, rb1);
            }
        }
        __syncthreads();
        cb = (cb == 2) ? 0 : cb + 1;
        ib = (ib == 2) ? 0 : ib + 1;
    }
    // epilogue
#pragma unroll
    for (int mi = 0; mi < 2; mi++) {
#pragma unroll
        for (int half = 0; half < 2; half++) {
            int row = r0 + wm * 32 + mi * 16 + g + half * 8;
            float ps = 0.f, pd = 0.f;
#pragma unroll
            for (int ni = 0; ni < 4; ni++) {
                int col = c0 + wn * 32 + ni * 8 + tg * 2;
#pragma unroll
                for (int q = 0; q < 2; q++) {
                    if (row < M && col + q < N) {
                        float v = acc[mi][ni][half * 2 + q] + (bias ? bias[col + q] : 0.f);
                        if (act == 1) v = fmaxf(v, 0.f);
                        else if (act == 2) v = v > 0.f ? v : expm1f(v);
                        if (OUT_HALF) {
                            __half hv = __float2half(v);
                            ((__half*)C_)[(long long)blockIdx.z * stC +
                                          (size_t)row * ldC + col + q] = hv;
                            if (FOLD) {
                                float vr = __half2float(hv);
                                ps = fmaf(vr, attS[col + q], ps);
                                pd = fmaf(vr, attD[col + q], pd);
                            }
                        } else {
                            ((float*)C_)[(long long)blockIdx.z * stC +
                                         (size_t)row * ldC + col + q] = v;
                            if (FOLD) {
                                ps = fmaf(v, attS[col + q], ps);
                                pd = fmaf(v, attD[col + q], pd);
                            }
                        }
                    }
                }
            }
            if (FOLD) {
                ps += __shfl_xor_sync(0xffffffffu, ps, 1);
                ps += __shfl_xor_sync(0xffffffffu, ps, 2);
                pd += __shfl_xor_sync(0xffffffffu, pd, 1);
                pd += __shfl_xor_sync(0xffffffffu, pd, 2);
                if (tg == 0 && row < M) {
                    atomicAdd(&outAS[row], ps);
                    atomicAdd(&outAD[row], pd);
                }
            }
        }
    }
}

// ---------------- TF32 GEMM (tail MLP): 64x128 tile, cp.async 3-stage --------
#define PAp 20
#define PBp 136
__global__ void __launch_bounds__(256) k_mma3(
    const float* __restrict__ A, const float* __restrict__ B,
    const float* __restrict__ bias, float* __restrict__ C,
    int M, int K, int N, int lda, int ldb, int ldC, int act) {
    __shared__ __align__(16) float sA[3][64 * PAp];
    __shared__ __align__(16) float sB[3][16 * PBp];
    int t = threadIdx.x;
    int warp = t >> 5, lane = t & 31;
    int g = lane >> 2, tg = lane & 3;
    int wm = warp >> 2, wn = warp & 3;
    int r0 = blockIdx.x * 64;
    int c0 = blockIdx.y * 128;

    int arow = t >> 2, acol = (t & 3) * 4;
    const float* aptr = A + (size_t)(r0 + arow) * lda + acol;
    int brow[2], bcol[2];
#pragma unroll
    for (int i = 0; i < 2; i++) {
        int id = t + i * 256;
        brow[i] = id >> 5;
        bcol[i] = (id & 31) * 4;
    }
    int niter = (K + 15) / 16;
    auto issue = [&](int s, int buf) {
        int kt = s * 16;
        cp16n(&sA[buf][arow * PAp + acol], aptr + kt, 16);
#pragma unroll
        for (int i = 0; i < 2; i++) {
            const float* src = B + (size_t)(kt + brow[i]) * ldb + c0 + bcol[i];
            int nb = 0;
            if (kt + brow[i] < K) {
                int v = N - (c0 + bcol[i]);
                nb = v >= 4 ? 16 : (v > 0 ? v * 4 : 0);
            }
            if (nb == 0) src = B;
            cp16n(&sB[buf][brow[i] * PBp + bcol[i]], src, nb);
        }
    };
#pragma unroll
    for (int s = 0; s < 2; s++) {
        if (s < niter) issue(s, s);
        asm volatile("cp.async.commit_group;\n");
    }
    float acc[2][4][4];
#pragma unroll
    for (int mi = 0; mi < 2; mi++)
#pragma unroll
        for (int ni = 0; ni < 4; ni++)
#pragma unroll
            for (int r = 0; r < 4; r++) acc[mi][ni][r] = 0.f;
    int cb = 0, ib = 2;
    for (int it = 0; it < niter; it++) {
        if (it + 2 < niter) issue(it + 2, ib);
        asm volatile("cp.async.commit_group;\n");
        asm volatile("cp.async.wait_group 2;\n");
        __syncthreads();
#pragma unroll
        for (int kk = 0; kk < 16; kk += 8) {
            uint32_t af[2][4];
#pragma unroll
            for (int mi = 0; mi < 2; mi++) {
                int br = wm * 32 + mi * 16;
                af[mi][0] = f2tf32(sA[cb][(br + g) * PAp + kk + tg]);
                af[mi][1] = f2tf32(sA[cb][(br + g + 8) * PAp + kk + tg]);
                af[mi][2] = f2tf32(sA[cb][(br + g) * PAp + kk + tg + 4]);
                af[mi][3] = f2tf32(sA[cb][(br + g + 8) * PAp + kk + tg + 4]);
            }
#pragma unroll
            for (int ni = 0; ni < 4; ni++) {
                int bc = wn * 32 + ni * 8 + g;
                uint32_t b0 = f2tf32(sB[cb][(kk + tg) * PBp + bc]);
                uint32_t bb = f2tf32(sB[cb][(kk + tg + 4) * PBp + bc]);
                MMA_TF32(acc[0][ni], af[0][0], af[0][1], af[0][2], af[0][3], b0, bb);
                MMA_TF32(acc[1][ni], af[1][0], af[1][1], af[1][2], af[1][3], b0, bb);
            }
        }
        __syncthreads();
        cb = (cb == 2) ? 0 : cb + 1;
        ib = (ib == 2) ? 0 : ib + 1;
    }
#pragma unroll
    for (int mi = 0; mi < 2; mi++) {
#pragma unroll
        for (int half = 0; half < 2; half++) {
            int row = r0 + wm * 32 + mi * 16 + g + half * 8;
            if (row >= M) continue;
#pragma unroll
            for (int ni = 0; ni < 4; ni++) {
                int col = c0 + wn * 32 + ni * 8 + tg * 2;
#pragma unroll
                for (int q = 0; q < 2; q++) {
                    if (col + q < N) {
                        float v = acc[mi][ni][half * 2 + q] + (bias ? bias[col + q] : 0.f);
                        if (act == 1) v = fmaxf(v, 0.f);
                        C[(size_t)row * ldC + col + q] = v;
                    }
                }
            }
        }
    }
}

// ---------------- layer 2: fused softmax + aggregation + readout ------------
__global__ void k_agg2_w(const float* __restrict__ b2, const float* __restrict__ wg,
                         const float* __restrict__ bg, const int* __restrict__ batch) {
    int n = blockIdx.x * 8 + (threadIdx.x >> 5);
    if (n >= N_NODES) return;
    int lane = threadIdx.x & 31;
    int p0 = g_OFF[n], p1 = g_OFF[n + 1];
    float adst = g_AD2[n];
    float m = -1e30f;
    for (int p = p0; p < p1; p++) {
        float e = g_AS2[g_CSRC[p]] + adst;
        e = e > 0.f ? e : 0.2f * e;
        m = fmaxf(m, e);
    }
    float den = 0.f;
    for (int p = p0; p < p1; p++) {
        float e = g_AS2[g_CSRC[p]] + adst;
        e = e > 0.f ? e : 0.2f * e;
        den += expf(e - m);
    }
    float rd = 1.f / (den + 1e-16f);
    float a0 = 0.f, a1 = 0.f, a2 = 0.f, a3 = 0.f;
    for (int p = p0; p < p1; p++) {
        int s = g_CSRC[p];
        float e = g_AS2[s] + adst;
        e = e > 0.f ? e : 0.2f * e;
        float al = expf(e - m) * rd;
        const float* hr = &g_H2[(size_t)s * OUT2];
        a0 = fmaf(al, hr[lane], a0);
        a1 = fmaf(al, hr[32 + lane], a1);
        a2 = fmaf(al, hr[64 + lane], a2);
        a3 = fmaf(al, hr[96 + lane], a3);
    }
    float v0 = fmaxf(a0 + b2[lane], 0.f);
    float v1 = fmaxf(a1 + b2[32 + lane], 0.f);
    float v2 = fmaxf(a2 + b2[64 + lane], 0.f);
    float v3 = fmaxf(a3 + b2[96 + lane], 0.f);
    float gp = v0 * wg[lane] + v1 * wg[32 + lane] + v2 * wg[64 + lane] + v3 * wg[96 + lane];
#pragma unroll
    for (int o = 16; o > 0; o >>= 1) gp += __shfl_xor_sync(0xffffffffu, gp, o);
    float w = 1.f / (1.f + expf(-(gp + bg[0])));
    int gr = batch[n];
    float* hs = &g_HSUM[(size_t)gr * OUT2];
    float* hm = &g_HMAX[(size_t)gr * OUT2];
    atomicAdd(&hs[lane], v0 * w);
    atomicAdd(&hs[32 + lane], v1 * w);
    atomicAdd(&hs[64 + lane], v2 * w);
    atomicAdd(&hs[96 + lane], v3 * w);
    atomicMax((int*)&hm[lane], __float_as_int(v0));
    atomicMax((int*)&hm[32 + lane], __float_as_int(v1));
    atomicMax((int*)&hm[64 + lane], __float_as_int(v2));
    atomicMax((int*)&hm[96 + lane], __float_as_int(v3));
}

// ---------------- tail ------------------------------------------------------
__global__ void k_concat() {
    int i = blockIdx.x * blockDim.x + threadIdx.x;
    if (i >= N_GRAPHS * 512) return;
    int g = i / 512, c = i - g * 512;
    float v;
    if (c < 128)      v = g_HSUM[g * 128 + c];
    else if (c < 256) v = g_HMAX[g * 128 + (c - 128)];
    else              v = g_XT[g * 256 + (c - 256)];
    g_XC[i] = v;
}
__global__ void k_out(const float* __restrict__ Wo, const float* __restrict__ bo,
                      float* __restrict__ out) {
    int g = blockIdx.x, lane = threadIdx.x;
    float s = 0.f;
    for (int k = lane; k < 256; k += 32) s += g_X2[g * 256 + k] * Wo[k];
#pragma unroll
    for (int o = 16; o > 0; o >>= 1) s += __shfl_down_sync(0xffffffffu, s, o);
    if (lane == 0) out[g] = s + bo[0];
}

// ---------------- host ------------------------------------------------------
static inline dim3 mma_grid(int M, int N, int Z = 1) {
    return dim3((M + 63) / 64, (N + 127) / 128, Z);
}

extern "C" void kernel_launch(void* const* d_in, const int* in_sizes, int n_in,
                              void* d_out, int out_size) {
    const float* x      = (const float*)d_in[0];
    const int*   ei     = (const int*)d_in[1];
    const int*   batch  = (const int*)d_in[2];
    const float* target = (const float*)d_in[3];
    const float* W1  = (const float*)d_in[4];
    const float* as1 = (const float*)d_in[5];
    const float* ad1 = (const float*)d_in[6];
    const float* b1  = (const float*)d_in[7];
    const float* W2  = (const float*)d_in[8];
    const float* as2 = (const float*)d_in[9];
    const float* ad2 = (const float*)d_in[10];
    const float* b2  = (const float*)d_in[11];
    const float* wg  = (const float*)d_in[12];
    const float* bg  = (const float*)d_in[13];
    const float* Wxt = (const float*)d_in[14];
    const float* bxt = (const float*)d_in[15];
    const float* Wf1 = (const float*)d_in[16];
    const float* bf1 = (const float*)d_in[17];
    const float* Wf2 = (const float*)d_in[18];
    const float* bf2 = (const float*)d_in[19];
    const float* Wo  = (const float*)d_in[20];
    const float* bo  = (const float*)d_in[21];
    float* out = (float*)d_out;

    __half *XAGGH, *H1OH, *W1TH, *W2TH;
    float *H2, *W2AS, *W2AD, *AS2, *AD2, *XT, *XC, *X1, *X2;
    cudaGetSymbolAddress((void**)&XAGGH, g_XAGGH);
    cudaGetSymbolAddress((void**)&H1OH, g_H1OH);
    cudaGetSymbolAddress((void**)&W1TH, g_W1TH);
    cudaGetSymbolAddress((void**)&W2TH, g_W2TH);
    cudaGetSymbolAddress((void**)&H2,  g_H2);
    cudaGetSymbolAddress((void**)&W2AS, g_W2AS);
    cudaGetSymbolAddress((void**)&W2AD, g_W2AD);
    cudaGetSymbolAddress((void**)&AS2, g_AS2);
    cudaGetSymbolAddress((void**)&AD2, g_AD2);
    cudaGetSymbolAddress((void**)&XT,  g_XT);
    cudaGetSymbolAddress((void**)&XC,  g_XC);
    cudaGetSymbolAddress((void**)&X1,  g_X1);
    cudaGetSymbolAddress((void**)&X2,  g_X2);

    // CSR build + zero accumulators (k_zero also sets DEG=1)
    k_zero<<<(N_GRAPHS * OUT2 + 255) / 256, 256>>>();
    k_hist<<<(N_EDGES + 255) / 256, 256>>>(ei);
    k_scan1<<<NB_SCAN, 1024>>>();
    k_scan2<<<1, 128>>>();
    k_scan3<<<(N_NODES + 255) / 256, 256>>>();
    k_scatter<<<(E_TOT + 255) / 256, 256>>>(ei);

    // weight prep (fp16 transposed copies for the big GEMMs)
    k_prep_att<<<(F_IN * 2 * H1N + 255) / 256, 256>>>(W1, as1, ad1);
    k_prep_w1t<<<(H1N * F_IN * F_IN + 255) / 256, 256>>>(W1);
    k_prep_w2t<<<(C1 * OUT2 + 255) / 256, 256>>>(W2);
    k_prep2v<<<(C1 + 255) / 256, 256>>>(W2, as2, ad2);

    // layer 1: logits -> fused softmax+agg (fp16 out) -> batched FP16 GEMM (+att2 fold)
    k_att1<<<(N_NODES + 7) / 8, 256>>>(x);
    k_aggx_w<<<(N_NODES + 7) / 8, 256>>>(x);
    k_mma_h<true, true><<<mma_grid(N_NODES, F_IN, H1N), 256>>>(
        XAGGH, W1TH, b1, H1OH, N_NODES, 80, F_IN, C1P, 80, H1OP, 2,
        80, 80 * 80, F_IN, F_IN,
        W2AS, W2AD, F_IN, AS2, AD2);

    // layer 2: H2 = H1O @ W2  [100000,780]x[780,128], FP16 inputs, fp32 out
    k_mma_h<false, false><<<mma_grid(N_NODES, OUT2), 256>>>(
        H1OH, W2TH, nullptr, H2, N_NODES, C1, OUT2, H1OP, H1OP, OUT2, 0,
        0, 0, 0, 0, nullptr, nullptr, 0, nullptr, nullptr);
    k_agg2_w<<<(N_NODES + 7) / 8, 256>>>(b2, wg, bg, batch);

    // tail MLP (small; TF32 path)
    k_mma3<<<mma_grid(N_GRAPHS, 256), 256>>>(target, Wxt, bxt, XT,
                                             N_GRAPHS, 1280, 256, 1280, 256, 256, 0);
    k_concat<<<(N_GRAPHS * 512 + 255) / 256, 256>>>();
    k_mma3<<<mma_grid(N_GRAPHS, 1024), 256>>>(XC, Wf1, bf1, X1,
                                              N_GRAPHS, 512, 1024, 512, 1024, 1024, 1);
    k_mma3<<<mma_grid(N_GRAPHS, 256), 256>>>(X1, Wf2, bf2, X2,
                                             N_GRAPHS, 1024, 256, 1024, 256, 256, 1);
    k_out<<<N_GRAPHS, 32>>>(Wo, bo, out);
}

// round 16
// speedup vs baseline: 1.3153x; 1.0219x over previous
#include <cuda_runtime.h>
#include <cuda_fp16.h>
#include <math.h>
#include <stdint.h>

#define N_NODES 100000
#define N_EDGES 400000
#define E_TOT   500000
#define N_GRAPHS 2048
#define F_IN 78
#define H1N 10
#define C1  780      // 10*78
#define C1P 800      // padded: 10 heads * 80
#define H1OP 784     // H1O half pitch (16B aligned)
#define OUT2 128
#define NB_SCAN 98   // ceil(100000/1024)

// ---------------- scratch (device globals; no allocation allowed) -----------
__device__ __align__(16) __half g_XAGGH[(N_NODES + 64) * C1P];  // fp16, pitch 80/head
__device__ __align__(16) __half g_H1OH[(N_NODES + 64) * H1OP];  // fp16 elu(gat1)
__device__ __align__(16) __half g_H2H[(N_NODES + 64) * OUT2];   // fp16 layer-2 pre-act
__device__ float g_ASD1[N_NODES * 2 * H1N];
__device__ float g_AS2[N_NODES], g_AD2[N_NODES];
__device__ int   g_DEG[N_NODES], g_INCL[N_NODES], g_BSUM[128], g_BOFF[128];
__device__ int   g_OFF[N_NODES + 1], g_CUR[N_NODES], g_CSRC[E_TOT];
__device__ float g_WATT[F_IN * 2 * H1N];
__device__ __align__(16) __half g_W1TH[(H1N * 80 + 128) * 80]; // W1 transposed [h][n][k], pads zero
__device__ __align__(16) __half g_W2TH[OUT2 * H1OP];           // W2 transposed [n][k], pads zero
__device__ float g_W2AS[C1], g_W2AD[C1];
__device__ __align__(16) float g_XT_unused[16];                // (kept for symmetry)
__device__ __align__(16) float g_XC[N_GRAPHS * 512];
__device__ __align__(16) float g_X1[N_GRAPHS * 1024];
__device__ __align__(16) float g_X2[N_GRAPHS * 256];

// ---------------- helpers ----------------------------------------------------
__device__ __forceinline__ uint32_t f2tf32(float v) {
    uint32_t u;
    asm("cvt.rna.tf32.f32 %0, %1;" : "=r"(u) : "f"(v));
    return u;
}
__device__ __forceinline__ void cp16n(void* dst, const void* src, int nbytes) {
    uint32_t d = (uint32_t)__cvta_generic_to_shared(dst);
    asm volatile("cp.async.cg.shared.global [%0], [%1], 16, %2;\n" :: "r"(d), "l"(src), "r"(nbytes));
}
#define MMA_TF32(ACC, A0, A1, A2, A3, B0, B1)                                   \
    asm volatile(                                                               \
        "mma.sync.aligned.m16n8k8.row.col.f32.tf32.tf32.f32 "                   \
        "{%0,%1,%2,%3}, {%4,%5,%6,%7}, {%8,%9}, {%0,%1,%2,%3};\n"               \
        : "+f"(ACC[0]), "+f"(ACC[1]), "+f"(ACC[2]), "+f"(ACC[3])                \
        : "r"(A0), "r"(A1), "r"(A2), "r"(A3), "r"(B0), "r"(B1))
#define MMA_F16(ACC, A0, A1, A2, A3, B0, B1)                                    \
    asm volatile(                                                               \
        "mma.sync.aligned.m16n8k16.row.col.f32.f16.f16.f32 "                    \
        "{%0,%1,%2,%3}, {%4,%5,%6,%7}, {%8,%9}, {%0,%1,%2,%3};\n"               \
        : "+f"(ACC[0]), "+f"(ACC[1]), "+f"(ACC[2]), "+f"(ACC[3])                \
        : "r"(A0), "r"(A1), "r"(A2), "r"(A3), "r"(B0), "r"(B1))

// ---------------- zero-init + CSR build -------------------------------------
__global__ void k_zero() {   // DEG self-loop, AS2/AD2, XC readout region
    int i = blockIdx.x * blockDim.x + threadIdx.x;
    if (i < N_GRAPHS * 256) {
        int g = i >> 8, c = i & 255;
        g_XC[g * 512 + c] = 0.f;     // c<128: wsum, c<256: max (relu'd vals >= 0)
    }
    if (i < N_NODES) { g_AS2[i] = 0.f; g_AD2[i] = 0.f; g_DEG[i] = 1; }
}
__global__ void k_hist(const int* __restrict__ ei) {
    int e = blockIdx.x * blockDim.x + threadIdx.x;
    if (e < N_EDGES) atomicAdd(&g_DEG[ei[N_EDGES + e]], 1);
}
__global__ void k_scan1() {
    __shared__ int sw[32];
    int i = blockIdx.x * 1024 + threadIdx.x;
    int v = (i < N_NODES) ? g_DEG[i] : 0;
    int lane = threadIdx.x & 31, w = threadIdx.x >> 5;
    int x = v;
#pragma unroll
    for (int o = 1; o < 32; o <<= 1) {
        int y = __shfl_up_sync(0xffffffffu, x, o);
        if (lane >= o) x += y;
    }
    if (lane == 31) sw[w] = x;
    __syncthreads();
    if (w == 0) {
        int s = sw[lane];
#pragma unroll
        for (int o = 1; o < 32; o <<= 1) {
            int y = __shfl_up_sync(0xffffffffu, s, o);
            if (lane >= o) s += y;
        }
        sw[lane] = s;
    }
    __syncthreads();
    if (w > 0) x += sw[w - 1];
    if (i < N_NODES) g_INCL[i] = x;
    if (threadIdx.x == 1023) g_BSUM[blockIdx.x] = x;
}
__global__ void k_scan2() {
    __shared__ int sw[4];
    int t = threadIdx.x;
    int v = (t < NB_SCAN) ? g_BSUM[t] : 0;
    int lane = t & 31, w = t >> 5;
    int x = v;
#pragma unroll
    for (int o = 1; o < 32; o <<= 1) {
        int y = __shfl_up_sync(0xffffffffu, x, o);
        if (lane >= o) x += y;
    }
    if (lane == 31) sw[w] = x;
    __syncthreads();
    int add = 0;
    for (int i = 0; i < w; i++) add += sw[i];
    x += add;
    if (t < NB_SCAN) g_BOFF[t] = x - v;
}
__global__ void k_scan3() {
    int i = blockIdx.x * blockDim.x + threadIdx.x;
    if (i < N_NODES) {
        int off = g_INCL[i] - g_DEG[i] + g_BOFF[i >> 10];
        g_OFF[i] = off;
        g_CUR[i] = off;
        if (i == 0) g_OFF[N_NODES] = E_TOT;
    }
}
__global__ void k_scatter(const int* __restrict__ ei) {
    int i = blockIdx.x * blockDim.x + threadIdx.x;
    if (i >= E_TOT) return;
    int s, d;
    if (i < N_EDGES) { s = ei[i]; d = ei[N_EDGES + i]; }
    else             { s = d = i - N_EDGES; }
    int pos = atomicAdd(&g_CUR[d], 1);
    g_CSRC[pos] = s;
}

// ---------------- merged weight prep -----------------------------------------
__global__ void k_prep(const float* __restrict__ W1, const float* __restrict__ as1,
                       const float* __restrict__ ad1, const float* __restrict__ W2,
                       const float* __restrict__ as2, const float* __restrict__ ad2) {
    int i = blockIdx.x * blockDim.x + threadIdx.x;
    if (i < F_IN * 2 * H1N) {           // attention-vector fold (x @ W1 a)
        int k = i / (2 * H1N), j = i - k * (2 * H1N);
        const float* a = (j < H1N) ? (as1 + j * F_IN) : (ad1 + (j - H1N) * F_IN);
        int h = (j < H1N) ? j : j - H1N;
        float s = 0.f;
        for (int d = 0; d < F_IN; d++) s += W1[k * C1 + h * F_IN + d] * a[d];
        g_WATT[i] = s;
    }
    if (i < H1N * F_IN * F_IN) {        // W1 -> [h][n 80][k 80] half (pads stay 0)
        int h = i / (F_IN * F_IN), r = i - h * F_IN * F_IN;
        int n = r / F_IN, k = r - n * F_IN;
        g_W1TH[(h * 80 + n) * 80 + k] = __float2half(W1[k * C1 + h * F_IN + n]);
    }
    if (i < C1 * OUT2) {                // W2 -> [n 128][k 784] half
        int k = i >> 7, n = i & 127;
        g_W2TH[n * H1OP + k] = __float2half(W2[i]);
    }
    if (i < C1) {                       // W2 @ a_src2 / a_dst2
        float s = 0.f, t = 0.f;
        for (int d = 0; d < OUT2; d++) {
            float w = W2[i * OUT2 + d];
            s = fmaf(w, as2[d], s);
            t = fmaf(w, ad2[d], t);
        }
        g_W2AS[i] = s;
        g_W2AD[i] = t;
    }
}

// ---------------- attention logits ------------------------------------------
__global__ void k_att1(const float* __restrict__ x) {
    __shared__ float sW[F_IN * 2 * H1N];
    __shared__ float sX[8 * F_IN];
    int tid = threadIdx.x, w = tid >> 5, lane = tid & 31;
    for (int i = tid; i < F_IN * 2 * H1N; i += 256) sW[i] = g_WATT[i];
    int n = blockIdx.x * 8 + w;
    if (n < N_NODES) {
        for (int d = lane; d < F_IN; d += 32) sX[w * F_IN + d] = x[(size_t)n * F_IN + d];
    }
    __syncthreads();
    if (n >= N_NODES || lane >= 2 * H1N) return;
    float s = 0.f;
    for (int d = 0; d < F_IN; d++)
        s = fmaf(sX[w * F_IN + d], sW[d * 2 * H1N + lane], s);
    g_ASD1[n * 2 * H1N + lane] = s;
}

// ---------------- layer 1: fused softmax + x-space aggregation (warp/node) --
__global__ void k_aggx_w(const float* __restrict__ x) {
    int n = blockIdx.x * 8 + (threadIdx.x >> 5);
    if (n >= N_NODES) return;
    int lane = threadIdx.x & 31;
    int p0 = g_OFF[n], p1 = g_OFF[n + 1];
    float adst = (lane < H1N) ? g_ASD1[n * 2 * H1N + H1N + lane] : 0.f;
    float m = -1e30f;
    for (int p = p0; p < p1; p++) {
        int s = g_CSRC[p];
        if (lane < H1N) {
            float e = g_ASD1[s * 2 * H1N + lane] + adst;
            e = e > 0.f ? e : 0.2f * e;
            m = fmaxf(m, e);
        }
    }
    float den = 0.f;
    for (int p = p0; p < p1; p++) {
        int s = g_CSRC[p];
        if (lane < H1N) {
            float e = g_ASD1[s * 2 * H1N + lane] + adst;
            e = e > 0.f ? e : 0.2f * e;
            den += expf(e - m);
        }
    }
    float rd = 1.f / (den + 1e-16f);
    float acc[H1N][3];
#pragma unroll
    for (int h = 0; h < H1N; h++) { acc[h][0] = 0.f; acc[h][1] = 0.f; acc[h][2] = 0.f; }
    for (int p = p0; p < p1; p++) {
        int s = g_CSRC[p];
        float al = 0.f;
        if (lane < H1N) {
            float e = g_ASD1[s * 2 * H1N + lane] + adst;
            e = e > 0.f ? e : 0.2f * e;
            al = expf(e - m) * rd;
        }
        const float* xr = &x[(size_t)s * F_IN];
        float xv0 = xr[lane];
        float xv1 = xr[32 + lane];
        float xv2 = (lane < F_IN - 64) ? xr[64 + lane] : 0.f;
#pragma unroll
        for (int h = 0; h < H1N; h++) {
            float a = __shfl_sync(0xffffffffu, al, h);
            acc[h][0] = fmaf(a, xv0, acc[h][0]);
            acc[h][1] = fmaf(a, xv1, acc[h][1]);
            acc[h][2] = fmaf(a, xv2, acc[h][2]);
        }
    }
    size_t base = (size_t)n * C1P;
#pragma unroll
    for (int h = 0; h < H1N; h++) {
        g_XAGGH[base + h * 80 + lane] = __float2half(acc[h][0]);
        g_XAGGH[base + h * 80 + 32 + lane] = __float2half(acc[h][1]);
        if (lane < F_IN - 64) g_XAGGH[base + h * 80 + 64 + lane] = __float2half(acc[h][2]);
    }
}

// ---------------- layer-1 GEMM: 64x80 tile fp16, per-head batched -------------
// H1O[:, h*78+n] = elu(XAGG_h(64x80) @ W1T_h(80->78) + b1); folds att2 dots.
#define PAH 40
#define PBH 40
__global__ void __launch_bounds__(256) k_gemm1(
    const __half* __restrict__ XA, const __half* __restrict__ W1T,
    const float* __restrict__ b1, __half* __restrict__ H1O,
    const float* __restrict__ W2AS, const float* __restrict__ W2AD,
    float* __restrict__ AS2, float* __restrict__ AD2) {
    __shared__ __align__(16) __half sA[3][64 * PAH];
    __shared__ __align__(16) __half sB[3][80 * PBH];
    int h = blockIdx.z;
    int r0 = blockIdx.x * 64;
    const __half* A = XA + h * 80;               // row pitch C1P
    const __half* B = W1T + (size_t)h * 80 * 80; // row pitch 80
    int t = threadIdx.x, warp = t >> 5, lane = t & 31, g = lane >> 2, tg = lane & 3;
    int wm = warp >> 1, wn = warp & 1;           // 4x2 warps -> 64x80

    auto issue = [&](int s, int buf) {
        int kt = s * 32;
        {   // A: 64 rows x 32 halves
            int row = t >> 2, koff = (t & 3) * 8;
            cp16n(&sA[buf][row * PAH + koff],
                  A + (size_t)(r0 + row) * C1P + kt + koff, 16);
        }
        // B: 80 n-rows x 32 halves = 320 chunks; zero-fill past K=80
#pragma unroll
        for (int i = 0; i < 2; i++) {
            int cc = t + i * 256;
            if (cc < 320) {
                int n = cc >> 2, koff = (cc & 3) * 8;
                int rem = 80 - (kt + koff);
                int nb = rem >= 8 ? 16 : (rem > 0 ? rem * 2 : 0);
                const __half* src = B + (size_t)n * 80 + kt + koff;
                if (nb == 0) src = B;
                cp16n(&sB[buf][n * PBH + koff], src, nb);
            }
        }
    };
    // 3-stage pipeline over niter = 3 (K=80: 32+32+16)
#pragma unroll
    for (int s = 0; s < 2; s++) { issue(s, s); asm volatile("cp.async.commit_group;\n"); }

    float acc[5][4];
#pragma unroll
    for (int ni = 0; ni < 5; ni++)
#pragma unroll
        for (int r = 0; r < 4; r++) acc[ni][r] = 0.f;

    int cb = 0, ib = 2;
#pragma unroll
    for (int it = 0; it < 3; it++) {
        if (it + 2 < 3) issue(it + 2, ib);
        asm volatile("cp.async.commit_group;\n");
        asm volatile("cp.async.wait_group 2;\n");
        __syncthreads();
#pragma unroll
        for (int kk = 0; kk < 32; kk += 16) {
            int br = wm * 16;
            const __half* a0 = &sA[cb][(br + g) * PAH + kk + 2 * tg];
            const __half* a1 = &sA[cb][(br + g + 8) * PAH + kk + 2 * tg];
            uint32_t ra0 = *(const uint32_t*)a0;
            uint32_t ra1 = *(const uint32_t*)a1;
            uint32_t ra2 = *(const uint32_t*)(a0 + 8);
            uint32_t ra3 = *(const uint32_t*)(a1 + 8);
#pragma unroll
            for (int ni = 0; ni < 5; ni++) {
                int bc = wn * 40 + ni * 8 + g;
                const __half* b0 = &sB[cb][bc * PBH + kk + 2 * tg];
                uint32_t rb0 = *(const uint32_t*)b0;
                uint32_t rb1 = *(const uint32_t*)(b0 + 8);
                MMA_F16(acc[ni], ra0, ra1, ra2, ra3, rb0, rb1);
            }
        }
        __syncthreads();
        cb = (cb == 2) ? 0 : cb + 1;
        ib = (ib == 2) ? 0 : ib + 1;
    }
    // epilogue: bias + elu -> H1O (half), fold att2 dots
    float ps[2] = {0.f, 0.f}, pd[2] = {0.f, 0.f};
#pragma unroll
    for (int half = 0; half < 2; half++) {
        int row = r0 + wm * 16 + g + half * 8;
        if (row >= N_NODES) continue;
#pragma unroll
        for (int ni = 0; ni < 5; ni++) {
            int col = wn * 40 + ni * 8 + tg * 2;
#pragma unroll
            for (int q = 0; q < 2; q++) {
                if (col + q < F_IN) {
                    int gc = h * F_IN + col + q;
                    float v = acc[ni][half * 2 + q] + b1[gc];
                    v = v > 0.f ? v : expm1f(v);
                    __half hv = __float2half(v);
                    H1O[(size_t)row * H1OP + gc] = hv;
                    float vr = __half2float(hv);
                    ps[half] = fmaf(vr, W2AS[gc], ps[half]);
                    pd[half] = fmaf(vr, W2AD[gc], pd[half]);
                }
            }
        }
    }
#pragma unroll
    for (int half = 0; half < 2; half++) {
        float p = ps[half], d = pd[half];
        p += __shfl_xor_sync(0xffffffffu, p, 1); p += __shfl_xor_sync(0xffffffffu, p, 2);
        d += __shfl_xor_sync(0xffffffffu, d, 1); d += __shfl_xor_sync(0xffffffffu, d, 2);
        int row = r0 + wm * 16 + g + half * 8;
        if (tg == 0 && row < N_NODES) {
            atomicAdd(&AS2[row], p);
            atomicAdd(&AD2[row], d);
        }
    }
}

// ---------------- FP16 GEMM: 64x128 tile (layer 2) ---------------------------
__global__ void __launch_bounds__(256) k_mma_h(
    const __half* __restrict__ A, const __half* __restrict__ B,
    __half* __restrict__ C, int M, int K, int N, int lda, int ldb, int ldC) {
    __shared__ __align__(16) __half sA[3][64 * PAH];
    __shared__ __align__(16) __half sB[3][128 * PBH];
    int t = threadIdx.x;
    int warp = t >> 5, lane = t & 31;
    int g = lane >> 2, tg = lane & 3;
    int wm = warp >> 2, wn = warp & 3;
    int r0 = blockIdx.x * 64;
    int c0 = blockIdx.y * 128;

    int niter = (K + 31) / 32;
    auto issue = [&](int s, int buf) {
        int kt = s * 32;
        {
            int row = t >> 2, koff = (t & 3) * 8;
            cp16n(&sA[buf][row * PAH + koff],
                  A + (size_t)(r0 + row) * lda + kt + koff, 16);
        }
#pragma unroll
        for (int i = 0; i < 2; i++) {
            int c = t + i * 256;
            int n = c >> 2, koff = (c & 3) * 8;
            const __half* src = B + (size_t)n * ldb + kt + koff;
            int nb = 0;
            if (c0 + n < N) {
                int rem = K - (kt + koff);
                nb = rem >= 8 ? 16 : (rem > 0 ? rem * 2 : 0);
            }
            if (nb == 0) src = B;
            cp16n(&sB[buf][n * PBH + koff], src, nb);
        }
    };
#pragma unroll
    for (int s = 0; s < 2; s++) {
        if (s < niter) issue(s, s);
        asm volatile("cp.async.commit_group;\n");
    }
    float acc[2][4][4];
#pragma unroll
    for (int mi = 0; mi < 2; mi++)
#pragma unroll
        for (int ni = 0; ni < 4; ni++)
#pragma unroll
            for (int r = 0; r < 4; r++) acc[mi][ni][r] = 0.f;
    int cb = 0, ib = 2;
    for (int it = 0; it < niter; it++) {
        if (it + 2 < niter) issue(it + 2, ib);
        asm volatile("cp.async.commit_group;\n");
        asm volatile("cp.async.wait_group 2;\n");
        __syncthreads();
#pragma unroll
        for (int kk = 0; kk < 32; kk += 16) {
            uint32_t af[2][4];
#pragma unroll
            for (int mi = 0; mi < 2; mi++) {
                int br = wm * 32 + mi * 16;
                const __half* a0 = &sA[cb][(br + g) * PAH + kk + 2 * tg];
                const __half* a1 = &sA[cb][(br + g + 8) * PAH + kk + 2 * tg];
                af[mi][0] = *(const uint32_t*)a0;
                af[mi][1] = *(const uint32_t*)a1;
                af[mi][2] = *(const uint32_t*)(a0 + 8);
                af[mi][3] = *(const uint32_t*)(a1 + 8);
            }
#pragma unroll
            for (int ni = 0; ni < 4; ni++) {
                int bc = wn * 32 + ni * 8 + g;
                const __half* b0 = &sB[cb][bc * PBH + kk + 2 * tg];
                uint32_t rb0 = *(const uint32_t*)b0;
                uint32_t rb1 = *(const uint32_t*)(b0 + 8);
                MMA_F16(acc[0][ni], af[0][0], af[0][1], af[0][2], af[0][3], rb0, rb1);
                MMA_F16(acc[1][ni], af[1][0], af[1][1], af[1][2], af[1][3], rb0, rb1);
            }
        }
        __syncthreads();
        cb = (cb == 2) ? 0 : cb + 1;
        ib = (ib == 2) ? 0 : ib + 1;
    }
#pragma unroll
    for (int mi = 0; mi < 2; mi++) {
#pragma unroll
        for (int half = 0; half < 2; half++) {
            int row = r0 + wm * 32 + mi * 16 + g + half * 8;
            if (row >= M) continue;
#pragma unroll
            for (int ni = 0; ni < 4; ni++) {
                int col = c0 + wn * 32 + ni * 8 + tg * 2;
#pragma unroll
                for (int q = 0; q < 2; q++) {
                    if (col + q < N)
                        C[(size_t)row * ldC + col + q] =
                            __float2half(acc[mi][ni][half * 2 + q]);
                }
            }
        }
    }
}

// ---------------- TF32 GEMM (tail MLP): 64x128 tile, cp.async 3-stage --------
#define PAp 20
#define PBp 136
__global__ void __launch_bounds__(256) k_mma3(
    const float* __restrict__ A, const float* __restrict__ B,
    const float* __restrict__ bias, float* __restrict__ C,
    int M, int K, int N, int lda, int ldb, int ldC, int act) {
    __shared__ __align__(16) float sA[3][64 * PAp];
    __shared__ __align__(16) float sB[3][16 * PBp];
    int t = threadIdx.x;
    int warp = t >> 5, lane = t & 31;
    int g = lane >> 2, tg = lane & 3;
    int wm = warp >> 2, wn = warp & 3;
    int r0 = blockIdx.x * 64;
    int c0 = blockIdx.y * 128;

    int arow = t >> 2, acol = (t & 3) * 4;
    const float* aptr = A + (size_t)(r0 + arow) * lda + acol;
    int brow[2], bcol[2];
#pragma unroll
    for (int i = 0; i < 2; i++) {
        int id = t + i * 256;
        brow[i] = id >> 5;
        bcol[i] = (id & 31) * 4;
    }
    int niter = (K + 15) / 16;
    auto issue = [&](int s, int buf) {
        int kt = s * 16;
        cp16n(&sA[buf][arow * PAp + acol], aptr + kt, 16);
#pragma unroll
        for (int i = 0; i < 2; i++) {
            const float* src = B + (size_t)(kt + brow[i]) * ldb + c0 + bcol[i];
            int nb = 0;
            if (kt + brow[i] < K) {
                int v = N - (c0 + bcol[i]);
                nb = v >= 4 ? 16 : (v > 0 ? v * 4 : 0);
            }
            if (nb == 0) src = B;
            cp16n(&sB[buf][brow[i] * PBp + bcol[i]], src, nb);
        }
    };
#pragma unroll
    for (int s = 0; s < 2; s++) {
        if (s < niter) issue(s, s);
        asm volatile("cp.async.commit_group;\n");
    }
    float acc[2][4][4];
#pragma unroll
    for (int mi = 0; mi < 2; mi++)
#pragma unroll
        for (int ni = 0; ni < 4; ni++)
#pragma unroll
            for (int r = 0; r < 4; r++) acc[mi][ni][r] = 0.f;
    int cb = 0, ib = 2;
    for (int it = 0; it < niter; it++) {
        if (it + 2 < niter) issue(it + 2, ib);
        asm volatile("cp.async.commit_group;\n");
        asm volatile("cp.async.wait_group 2;\n");
        __syncthreads();
#pragma unroll
        for (int kk = 0; kk < 16; kk += 8) {
            uint32_t af[2][4];
#pragma unroll
            for (int mi = 0; mi < 2; mi++) {
                int br = wm * 32 + mi * 16;
                af[mi][0] = f2tf32(sA[cb][(br + g) * PAp + kk + tg]);
                af[mi][1] = f2tf32(sA[cb][(br + g + 8) * PAp + kk + tg]);
                af[mi][2] = f2tf32(sA[cb][(br + g) * PAp + kk + tg + 4]);
                af[mi][3] = f2tf32(sA[cb][(br + g + 8) * PAp + kk + tg + 4]);
            }
#pragma unroll
            for (int ni = 0; ni < 4; ni++) {
                int bc = wn * 32 + ni * 8 + g;
                uint32_t b0 = f2tf32(sB[cb][(kk + tg) * PBp + bc]);
                uint32_t bb = f2tf32(sB[cb][(kk + tg + 4) * PBp + bc]);
                MMA_TF32(acc[0][ni], af[0][0], af[0][1], af[0][2], af[0][3], b0, bb);
                MMA_TF32(acc[1][ni], af[1][0], af[1][1], af[1][2], af[1][3], b0, bb);
            }
        }
        __syncthreads();
        cb = (cb == 2) ? 0 : cb + 1;
        ib = (ib == 2) ? 0 : ib + 1;
    }
#pragma unroll
    for (int mi = 0; mi < 2; mi++) {
#pragma unroll
        for (int half = 0; half < 2; half++) {
            int row = r0 + wm * 32 + mi * 16 + g + half * 8;
            if (row >= M) continue;
#pragma unroll
            for (int ni = 0; ni < 4; ni++) {
                int col = c0 + wn * 32 + ni * 8 + tg * 2;
#pragma unroll
                for (int q = 0; q < 2; q++) {
                    if (col + q < N) {
                        float v = acc[mi][ni][half * 2 + q] + (bias ? bias[col + q] : 0.f);
                        if (act == 1) v = fmaxf(v, 0.f);
                        C[(size_t)row * ldC + col + q] = v;
                    }
                }
            }
        }
    }
}

// ---------------- layer 2: fused softmax + aggregation + readout -> XC ------
__global__ void k_agg2_w(const float* __restrict__ b2, const float* __restrict__ wg,
                         const float* __restrict__ bg, const int* __restrict__ batch) {
    int n = blockIdx.x * 8 + (threadIdx.x >> 5);
    if (n >= N_NODES) return;
    int lane = threadIdx.x & 31;
    int p0 = g_OFF[n], p1 = g_OFF[n + 1];
    float adst = g_AD2[n];
    float m = -1e30f;
    for (int p = p0; p < p1; p++) {
        float e = g_AS2[g_CSRC[p]] + adst;
        e = e > 0.f ? e : 0.2f * e;
        m = fmaxf(m, e);
    }
    float den = 0.f;
    for (int p = p0; p < p1; p++) {
        float e = g_AS2[g_CSRC[p]] + adst;
        e = e > 0.f ? e : 0.2f * e;
        den += expf(e - m);
    }
    float rd = 1.f / (den + 1e-16f);
    float a0 = 0.f, a1 = 0.f, a2 = 0.f, a3 = 0.f;
    for (int p = p0; p < p1; p++) {
        int s = g_CSRC[p];
        float e = g_AS2[s] + adst;
        e = e > 0.f ? e : 0.2f * e;
        float al = expf(e - m) * rd;
        const __half* hr = &g_H2H[(size_t)s * OUT2];
        a0 = fmaf(al, __half2float(hr[lane]), a0);
        a1 = fmaf(al, __half2float(hr[32 + lane]), a1);
        a2 = fmaf(al, __half2float(hr[64 + lane]), a2);
        a3 = fmaf(al, __half2float(hr[96 + lane]), a3);
    }
    float v0 = fmaxf(a0 + b2[lane], 0.f);
    float v1 = fmaxf(a1 + b2[32 + lane], 0.f);
    float v2 = fmaxf(a2 + b2[64 + lane], 0.f);
    float v3 = fmaxf(a3 + b2[96 + lane], 0.f);
    float gp = v0 * wg[lane] + v1 * wg[32 + lane] + v2 * wg[64 + lane] + v3 * wg[96 + lane];
#pragma unroll
    for (int o = 16; o > 0; o >>= 1) gp += __shfl_xor_sync(0xffffffffu, gp, o);
    float w = 1.f / (1.f + expf(-(gp + bg[0])));
    int gr = batch[n];
    float* hs = &g_XC[(size_t)gr * 512];          // wsum at [0,128)
    float* hm = &g_XC[(size_t)gr * 512 + 128];    // max  at [128,256)
    atomicAdd(&hs[lane], v0 * w);
    atomicAdd(&hs[32 + lane], v1 * w);
    atomicAdd(&hs[64 + lane], v2 * w);
    atomicAdd(&hs[96 + lane], v3 * w);
    atomicMax((int*)&hm[lane], __float_as_int(v0));
    atomicMax((int*)&hm[32 + lane], __float_as_int(v1));
    atomicMax((int*)&hm[64 + lane], __float_as_int(v2));
    atomicMax((int*)&hm[96 + lane], __float_as_int(v3));
}

// ---------------- tail ------------------------------------------------------
__global__ void k_out(const float* __restrict__ Wo, const float* __restrict__ bo,
                      float* __restrict__ out) {
    int g = blockIdx.x, lane = threadIdx.x;
    float s = 0.f;
    for (int k = lane; k < 256; k += 32) s += g_X2[g * 256 + k] * Wo[k];
#pragma unroll
    for (int o = 16; o > 0; o >>= 1) s += __shfl_down_sync(0xffffffffu, s, o);
    if (lane == 0) out[g] = s + bo[0];
}

// ---------------- host ------------------------------------------------------
static inline dim3 mma_grid(int M, int N, int Z = 1) {
    return dim3((M + 63) / 64, (N + 127) / 128, Z);
}

extern "C" void kernel_launch(void* const* d_in, const int* in_sizes, int n_in,
                              void* d_out, int out_size) {
    const float* x      = (const float*)d_in[0];
    const int*   ei     = (const int*)d_in[1];
    const int*   batch  = (const int*)d_in[2];
    const float* target = (const float*)d_in[3];
    const float* W1  = (const float*)d_in[4];
    const float* as1 = (const float*)d_in[5];
    const float* ad1 = (const float*)d_in[6];
    const float* b1  = (const float*)d_in[7];
    const float* W2  = (const float*)d_in[8];
    const float* as2 = (const float*)d_in[9];
    const float* ad2 = (const float*)d_in[10];
    const float* b2  = (const float*)d_in[11];
    const float* wg  = (const float*)d_in[12];
    const float* bg  = (const float*)d_in[13];
    const float* Wxt = (const float*)d_in[14];
    const float* bxt = (const float*)d_in[15];
    const float* Wf1 = (const float*)d_in[16];
    const float* bf1 = (const float*)d_in[17];
    const float* Wf2 = (const float*)d_in[18];
    const float* bf2 = (const float*)d_in[19];
    const float* Wo  = (const float*)d_in[20];
    const float* bo  = (const float*)d_in[21];
    float* out = (float*)d_out;

    __half *XAGGH, *H1OH, *H2H, *W1TH, *W2TH;
    float *W2AS, *W2AD, *AS2, *AD2, *XC, *X1, *X2;
    cudaGetSymbolAddress((void**)&XAGGH, g_XAGGH);
    cudaGetSymbolAddress((void**)&H1OH, g_H1OH);
    cudaGetSymbolAddress((void**)&H2H, g_H2H);
    cudaGetSymbolAddress((void**)&W1TH, g_W1TH);
    cudaGetSymbolAddress((void**)&W2TH, g_W2TH);
    cudaGetSymbolAddress((void**)&W2AS, g_W2AS);
    cudaGetSymbolAddress((void**)&W2AD, g_W2AD);
    cudaGetSymbolAddress((void**)&AS2, g_AS2);
    cudaGetSymbolAddress((void**)&AD2, g_AD2);
    cudaGetSymbolAddress((void**)&XC,  g_XC);
    cudaGetSymbolAddress((void**)&X1,  g_X1);
    cudaGetSymbolAddress((void**)&X2,  g_X2);

    // CSR build + zero accumulators (k_zero also sets DEG=1, zeroes XC readout)
    k_zero<<<(N_GRAPHS * 256 + 255) / 256, 256>>>();
    k_hist<<<(N_EDGES + 255) / 256, 256>>>(ei);
    k_scan1<<<NB_SCAN, 1024>>>();
    k_scan2<<<1, 128>>>();
    k_scan3<<<(N_NODES + 255) / 256, 256>>>();
    k_scatter<<<(E_TOT + 255) / 256, 256>>>(ei);

    // merged weight prep
    k_prep<<<(C1 * OUT2 + 255) / 256, 256>>>(W1, as1, ad1, W2, as2, ad2);

    // layer 1: logits -> fused softmax+agg (fp16) -> 64x80 fp16 GEMM (+att2 fold)
    k_att1<<<(N_NODES + 7) / 8, 256>>>(x);
    k_aggx_w<<<(N_NODES + 7) / 8, 256>>>(x);
    k_gemm1<<<dim3((N_NODES + 63) / 64, 1, H1N), 256>>>(
        XAGGH, W1TH, b1, H1OH, W2AS, W2AD, AS2, AD2);

    // layer 2: H2 = H1O @ W2  [100000,780]x[780,128] fp16 in/out
    k_mma_h<<<mma_grid(N_NODES, OUT2), 256>>>(
        H1OH, W2TH, H2H, N_NODES, C1, OUT2, H1OP, H1OP, OUT2);
    k_agg2_w<<<(N_NODES + 7) / 8, 256>>>(b2, wg, bg, batch);

    // tail MLP: XT written straight into XC[:, 256:512]
    k_mma3<<<mma_grid(N_GRAPHS, 256), 256>>>(target, Wxt, bxt, XC + 256,
                                             N_GRAPHS, 1280, 256, 1280, 256, 512, 0);
    k_mma3<<<mma_grid(N_GRAPHS, 1024), 256>>>(XC, Wf1, bf1, X1,
                                              N_GRAPHS, 512, 1024, 512, 1024, 1024, 1);
    k_mma3<<<mma_grid(N_GRAPHS, 256), 256>>>(X1, Wf2, bf2, X2,
                                             N_GRAPHS, 1024, 256, 1024, 256, 256, 1);
    k_out<<<N_GRAPHS, 32>>>(Wo, bo, out);
}